// round 5
// baseline (speedup 1.0000x reference)
#include <cuda_runtime.h>
#include <math.h>
#include <float.h>

#define NMAX 20000
#define EMAX 320000
#define H 128
#define T 4
#define FIN 32
#define FULLM 0xffffffffu
#define NB 132   // resident blocks for fused setup

typedef unsigned long long ull;

// ---------------- f32x2 packed helpers ----------------
__device__ __forceinline__ ull packf2(float lo, float hi) {
    ull r;
    asm("mov.b64 %0, {%1, %2};" : "=l"(r) : "r"(__float_as_uint(lo)), "r"(__float_as_uint(hi)));
    return r;
}
__device__ __forceinline__ void unpackf2(ull v, float& lo, float& hi) {
    unsigned int a, b;
    asm("mov.b64 {%0, %1}, %2;" : "=r"(a), "=r"(b) : "l"(v));
    lo = __uint_as_float(a); hi = __uint_as_float(b);
}
__device__ __forceinline__ ull fma2(ull a, ull b, ull c) {
    ull d;
    asm("fma.rn.f32x2 %0, %1, %2, %3;" : "=l"(d) : "l"(a), "l"(b), "l"(c));
    return d;
}
__device__ __forceinline__ ull add2(ull a, ull b) {
    ull d;
    asm("add.rn.f32x2 %0, %1, %2;" : "=l"(d) : "l"(a), "l"(b));
    return d;
}

// ---------------- device scratch ----------------
__device__ float g_avg_log;
__device__ float g_enc[5 * FIN];
__device__ int   g_deg[NMAX];
__device__ int   g_off[NMAX + 1];
__device__ int   g_fill[NMAX];
__device__ int   g_csr[EMAX];                 // packed: src | (bond<<27)
__device__ int   g_part[NB];
__device__ int   g_poff[NB];
__device__ float g_a0[(size_t)NMAX * H];
__device__ float g_p [(size_t)NMAX * H];
__device__ float g_agg[(size_t)NMAX * T * 5 * FIN];
__device__ float g_y[(size_t)NMAX * H];
__device__ unsigned int g_bar;
__device__ unsigned int g_done;

// ---------------- fused setup: zero + hist + PRE + scan + scatter ----------------
__device__ __forceinline__ void grid_bar(unsigned target) {
    __syncthreads();
    if (threadIdx.x == 0) {
        __threadfence();
        atomicAdd(&g_bar, 1u);
        while (*((volatile unsigned int*)&g_bar) < target) { }
        __threadfence();
    }
    __syncthreads();
}

__global__ void __launch_bounds__(256) k_setup(
    const int* __restrict__ dst, const int* __restrict__ src,
    const int* __restrict__ bond,
    const float* __restrict__ atom_x,
    const float* __restrict__ pre_w1, const float* __restrict__ pre_b1,
    int N, int E) {
    const int tid = threadIdx.x, b = blockIdx.x;
    const int gsz = NB * 256;
    const int gid = b * 256 + tid;
    __shared__ int sh[256];

    // P0: zero degree counters
    for (int i = gid; i < N; i += gsz) __stcg(&g_deg[i], 0);
    grid_bar(NB * 1);

    // P1: degree histogram
    for (int e = gid; e < E; e += gsz) atomicAdd(&g_deg[__ldg(&dst[e])], 1);

    // PRE (independent of hist): A0 = b1 + W1a.x, P = W1b.x
    {
        const int l = tid & 31;
        const int w = tid >> 5;
        const int t = w & 3;
        float w1a[FIN], w1b[FIN];
#pragma unroll
        for (int f = 0; f < FIN; f++) w1a[f] = pre_w1[(t * 96 + f) * FIN + l];
#pragma unroll
        for (int f = 0; f < FIN; f++) w1b[f] = pre_w1[(t * 96 + 32 + f) * FIN + l];
        const float b1 = pre_b1[t * FIN + l];
        for (int n = b * 2 + (w >> 2); n < N; n += NB * 2) {
            float x = atom_x[n * H + t * FIN + l];
            float a0 = b1, p = 0.f;
#pragma unroll
            for (int f = 0; f < FIN; f++) {
                float xf = __shfl_sync(FULLM, x, f);
                a0 += xf * w1a[f];
                p  += xf * w1b[f];
            }
            g_a0[n * H + t * FIN + l] = a0;
            g_p [n * H + t * FIN + l] = p;
        }
    }
    grid_bar(NB * 2);

    // P2: per-block chunk scan (chunk <= 256)
    const int chunk = (N + NB - 1) / NB;
    const int i = b * chunk + tid;
    int v = (tid < chunk && i < N) ? __ldcg(&g_deg[i]) : 0;
    sh[tid] = v;
    __syncthreads();
    for (int off = 1; off < 256; off <<= 1) {
        int tv = (tid >= off) ? sh[tid - off] : 0;
        __syncthreads();
        sh[tid] += tv;
        __syncthreads();
    }
    int local_excl = sh[tid] - v;
    if (tid == 255) __stcg(&g_part[b], sh[255]);
    grid_bar(NB * 3);

    // P3: block 0 scans block totals
    if (b == 0) {
        int v2 = (tid < NB) ? __ldcg(&g_part[tid]) : 0;
        sh[tid] = v2;
        __syncthreads();
        for (int off = 1; off < 256; off <<= 1) {
            int tv = (tid >= off) ? sh[tid - off] : 0;
            __syncthreads();
            sh[tid] += tv;
            __syncthreads();
        }
        if (tid < NB) __stcg(&g_poff[tid], sh[tid] - v2);
        if (tid == 0) __stcg(&g_off[N], E);
    }
    grid_bar(NB * 4);

    // P4: finalize offsets
    {
        int po = __ldcg(&g_poff[b]);
        if (tid < chunk && i < N) {
            int vv = local_excl + po;
            __stcg(&g_off[i], vv);
            __stcg(&g_fill[i], vv);
        }
    }
    grid_bar(NB * 5);

    // P5: scatter edges into CSR
    for (int e = gid; e < E; e += gsz) {
        int d = __ldg(&dst[e]);
        int p = atomicAdd(&g_fill[d], 1);
        __stcg(&g_csr[p], __ldg(&src[e]) | (__ldg(&bond[e]) << 27));
    }

    // reset barrier state for next graph replay
    __syncthreads();
    if (tid == 0) {
        if (atomicAdd(&g_done, 1u) == NB - 1) {
            atomicExch(&g_bar, 0u);
            atomicExch(&g_done, 0u);
        }
    }
}

// ---------------- scalars ----------------
__global__ void k_scalars(const int* __restrict__ mol_deg,
                          const float* __restrict__ bond_emb,
                          const float* __restrict__ enc_w,
                          const float* __restrict__ enc_b) {
    __shared__ float s_num[256], s_den[256];
    int tid = threadIdx.x;
    float num = 0.f, den = 0.f;
    if (tid < 128) {
        float d = (float)mol_deg[tid];
        num = logf((float)tid + 1.0f) * d;
        den = d;
    }
    s_num[tid] = num; s_den[tid] = den;
    __syncthreads();
    for (int off = 128; off > 0; off >>= 1) {
        if (tid < off) { s_num[tid] += s_num[tid + off]; s_den[tid] += s_den[tid + off]; }
        __syncthreads();
    }
    if (tid == 0) g_avg_log = s_num[0] / s_den[0];

    if (tid < 5 * FIN) {
        int b = tid >> 5, g = tid & 31;
        float a = enc_b[g];
        for (int k = 0; k < H; k++) a += bond_emb[b * H + k] * enc_w[k * FIN + g];
        g_enc[b * FIN + g] = a;
    }
}

// ---------------- edge loop: dual-node, edge-major staging, paired weights ----------------
// w2d[j] = (w_{2j}, w_{2j+1}); per-edge dot: both FMA2 halves accumulate the SAME edge,
// horizontal add at the end. Halves the weight register footprint.
__device__ __forceinline__ float dot_edge(const float* buf, const ull* w2d, float b2) {
    ull acc = 0ull;
#pragma unroll
    for (int j = 0; j < 8; j++) {
        ulonglong2 v = *(const ulonglong2*)&buf[4 * j];
        acc = fma2(v.x, w2d[2 * j], acc);
        acc = fma2(v.y, w2d[2 * j + 1], acc);
    }
    float lo, hi; unpackf2(acc, lo, hi);
    return lo + hi + b2;
}

__global__ void __launch_bounds__(128, 6) k_agg(
    const float* __restrict__ pre_w1,
    const float* __restrict__ pre_w2, const float* __restrict__ pre_b2, int N) {
    const int l = threadIdx.x & 31;
    const int t = threadIdx.x >> 5;
    __shared__ __align__(16) float rs[4][2][4][32];   // [warp][parity][edge-slot][feature]

    ull w2d[16];
#pragma unroll
    for (int j = 0; j < 16; j++)
        w2d[j] = packf2(pre_w2[(t * FIN + 2 * j) * FIN + l],
                        pre_w2[(t * FIN + 2 * j + 1) * FIN + l]);
    const float b2 = pre_b2[t * FIN + l];

    float evc0, evc1, evc2, evc3, evc4;
    {
        float w1c[FIN];
#pragma unroll
        for (int f = 0; f < FIN; f++) w1c[f] = pre_w1[(t * 96 + 64 + f) * FIN + l];
        float ev[5];
#pragma unroll
        for (int b = 0; b < 5; b++) {
            float et = g_enc[b * FIN + l];
            float a = 0.f;
#pragma unroll
            for (int f = 0; f < FIN; f++) a += __shfl_sync(FULLM, et, f) * w1c[f];
            ev[b] = a;
        }
        evc0 = ev[0]; evc1 = ev[1]; evc2 = ev[2]; evc3 = ev[3]; evc4 = ev[4];
    }
    const int off = t * FIN + l;
    const int half = (N + 1) >> 1;

#define EVSEL(bb) ({ float _e = evc0; _e = ((bb)==1)?evc1:_e; _e = ((bb)==2)?evc2:_e; \
                     _e = ((bb)==3)?evc3:_e; _e = ((bb)==4)?evc4:_e; _e; })

    for (int n = blockIdx.x; n < half; n += gridDim.x) {
        const int nA = n, nB = n + half;
        const bool hasB = nB < N;
        float a0A = g_a0[nA * H + off];
        int e0A = g_off[nA], e1A = g_off[nA + 1];
        float a0B = 0.f; int e0B = 0, e1B = 0;
        if (hasB) { a0B = g_a0[nB * H + off]; e0B = g_off[nB]; e1B = g_off[nB + 1]; }
        const int cntA = e1A - e0A, cntB = e1B - e0B;
        const int pAcnt = cntA >> 1, pBcnt = cntB >> 1;
        const int np = max(pAcnt, pBcnt);

        float sA = 0.f, qA = 0.f, sB = 0.f, qB = 0.f;
        float minA = FLT_MAX, maxA = -FLT_MAX, minB = FLT_MAX, maxB = -FLT_MAX;

        float paA = 0.f, pbA = 0.f, paB = 0.f, pbB = 0.f;
        int baA = 0, bbA = 0, baB = 0, bbB = 0;
        if (pAcnt > 0) {
            int k0 = g_csr[e0A], k1 = g_csr[e0A + 1];
            baA = k0 >> 27; bbA = k1 >> 27;
            paA = g_p[(k0 & 0x07ffffff) * H + off];
            pbA = g_p[(k1 & 0x07ffffff) * H + off];
        }
        if (pBcnt > 0) {
            int k0 = g_csr[e0B], k1 = g_csr[e0B + 1];
            baB = k0 >> 27; bbB = k1 >> 27;
            paB = g_p[(k0 & 0x07ffffff) * H + off];
            pbB = g_p[(k1 & 0x07ffffff) * H + off];
        }

        for (int i = 0; i < np; i++) {
            const int par = i & 1;
            const bool dA = i < pAcnt, dB = i < pBcnt;
            if (dA) {
                rs[t][par][0][l] = fmaxf(a0A + EVSEL(baA) + paA, 0.f);
                rs[t][par][1][l] = fmaxf(a0A + EVSEL(bbA) + pbA, 0.f);
            }
            if (dB) {
                rs[t][par][2][l] = fmaxf(a0B + EVSEL(baB) + paB, 0.f);
                rs[t][par][3][l] = fmaxf(a0B + EVSEL(bbB) + pbB, 0.f);
            }
            if (i + 1 < pAcnt) {
                int idx = e0A + 2 * (i + 1);
                int k0 = g_csr[idx], k1 = g_csr[idx + 1];
                baA = k0 >> 27; bbA = k1 >> 27;
                paA = g_p[(k0 & 0x07ffffff) * H + off];
                pbA = g_p[(k1 & 0x07ffffff) * H + off];
            }
            if (i + 1 < pBcnt) {
                int idx = e0B + 2 * (i + 1);
                int k0 = g_csr[idx], k1 = g_csr[idx + 1];
                baB = k0 >> 27; bbB = k1 >> 27;
                paB = g_p[(k0 & 0x07ffffff) * H + off];
                pbB = g_p[(k1 & 0x07ffffff) * H + off];
            }
            __syncwarp();
            if (dA) {
                float m0 = dot_edge(rs[t][par][0], w2d, b2);
                float m1 = dot_edge(rs[t][par][1], w2d, b2);
                sA += m0 + m1;
                qA = fmaf(m0, m0, qA); qA = fmaf(m1, m1, qA);
                minA = fminf(minA, fminf(m0, m1));
                maxA = fmaxf(maxA, fmaxf(m0, m1));
            }
            if (dB) {
                float m0 = dot_edge(rs[t][par][2], w2d, b2);
                float m1 = dot_edge(rs[t][par][3], w2d, b2);
                sB += m0 + m1;
                qB = fmaf(m0, m0, qB); qB = fmaf(m1, m1, qB);
                minB = fminf(minB, fminf(m0, m1));
                maxB = fmaxf(maxB, fmaxf(m0, m1));
            }
        }

        const bool tA = (cntA & 1) != 0, tB = (cntB & 1) != 0;
        if (tA | tB) {
            const int par = np & 1;
            if (tA) {
                int k = g_csr[e1A - 1];
                float p = g_p[(k & 0x07ffffff) * H + off];
                rs[t][par][0][l] = fmaxf(a0A + EVSEL(k >> 27) + p, 0.f);
            }
            if (tB) {
                int k = g_csr[e1B - 1];
                float p = g_p[(k & 0x07ffffff) * H + off];
                rs[t][par][2][l] = fmaxf(a0B + EVSEL(k >> 27) + p, 0.f);
            }
            __syncwarp();
            if (tA) {
                float m0 = dot_edge(rs[t][par][0], w2d, b2);
                sA += m0; qA = fmaf(m0, m0, qA);
                minA = fminf(minA, m0); maxA = fmaxf(maxA, m0);
            }
            if (tB) {
                float m0 = dot_edge(rs[t][par][2], w2d, b2);
                sB += m0; qB = fmaf(m0, m0, qB);
                minB = fminf(minB, m0); maxB = fmaxf(maxB, m0);
            }
        }

        {
            float c1 = fmaxf((float)cntA, 1.f);
            float mean = sA / c1;
            float stdv = sqrtf(fmaxf(qA / c1 - mean * mean, 0.f) + 1e-5f);
            float mn = minA, mx = maxA;
            if (cntA == 0) { mn = 0.f; mx = 0.f; }
            float* o = g_agg + (size_t)(nA * T + t) * 5 * FIN + l;
            o[0 * FIN] = sA; o[1 * FIN] = mean; o[2 * FIN] = mn;
            o[3 * FIN] = mx; o[4 * FIN] = stdv;
        }
        if (hasB) {
            float c1 = fmaxf((float)cntB, 1.f);
            float mean = sB / c1;
            float stdv = sqrtf(fmaxf(qB / c1 - mean * mean, 0.f) + 1e-5f);
            float mn = minB, mx = maxB;
            if (cntB == 0) { mn = 0.f; mx = 0.f; }
            float* o = g_agg + (size_t)(nB * T + t) * 5 * FIN + l;
            o[0 * FIN] = sB; o[1 * FIN] = mean; o[2 * FIN] = mn;
            o[3 * FIN] = mx; o[4 * FIN] = stdv;
        }
    }
#undef EVSEL
}

// ---------------- post-MLP: factored scalers, 192-feature staging ----------------
__global__ void __launch_bounds__(128) k_post(
    const float* __restrict__ atom_x,
    const float* __restrict__ post_w1, const float* __restrict__ post_b1,
    const float* __restrict__ post_w2, const float* __restrict__ post_b2,
    int N) {
    const int t = blockIdx.y;
    const int w = threadIdx.x >> 5;
    const int g = threadIdx.x & 31;
    __shared__ __align__(16) float2 st2[4][4][192];   // [warp][pair][feature] (lo=node j, hi=node j+4)
    __shared__ float s1s[4][8], s2s[4][8];

    const float avg = g_avg_log;
    const float* w1 = post_w1 + (size_t)t * 512 * FIN;
    const float b1 = post_b1[t * FIN + g];
    const float b2v = post_b2[t * FIN + g];
    float w2v[FIN];
#pragma unroll
    for (int f = 0; f < FIN; f++) w2v[f] = post_w2[(t * FIN + f) * FIN + g];
    const int base = blockIdx.x * 64 + w * 16;

    for (int grp = 0; grp < 2; grp++) {
        int n0 = base + grp * 8;
#pragma unroll
        for (int j = 0; j < 8; j++) {
            int n = min(n0 + j, N - 1);
            int cnt = g_deg[n];
            float c1 = fmaxf((float)cnt, 1.f);
            float logd = logf(c1 + 1.f);
            s1s[w][j] = logd / avg;
            s2s[w][j] = avg / logd;
            float* dstp = ((float*)&st2[w][j & 3][0]) + (j >> 2);
            dstp[2 * g] = atom_x[n * H + t * FIN + g];
            const float* ag = g_agg + (size_t)(n * T + t) * 5 * FIN;
#pragma unroll
            for (int a = 0; a < 5; a++)
                dstp[2 * (32 + a * FIN + g)] = ag[a * FIN + g];
        }
        __syncwarp();

        ull accI0 = packf2(b1, b1);
        ull accI1 = accI0, accI2 = accI0, accI3 = accI0;
        ull accA0 = 0, accA1 = 0, accA2 = 0, accA3 = 0;
        ull accT0 = 0, accT1 = 0, accT2 = 0, accT3 = 0;

        // x part: rows 0..31 (accI only)
#pragma unroll 4
        for (int f2 = 0; f2 < 16; f2++) {
            int f = 2 * f2;
            ulonglong2 v0 = *(const ulonglong2*)&st2[w][0][f];
            ulonglong2 v1 = *(const ulonglong2*)&st2[w][1][f];
            ulonglong2 v2 = *(const ulonglong2*)&st2[w][2][f];
            ulonglong2 v3 = *(const ulonglong2*)&st2[w][3][f];
            float wv0 = w1[f * FIN + g];
            float wv1 = w1[(f + 1) * FIN + g];
            ull wd0 = packf2(wv0, wv0), wd1 = packf2(wv1, wv1);
            accI0 = fma2(v0.x, wd0, accI0); accI0 = fma2(v0.y, wd1, accI0);
            accI1 = fma2(v1.x, wd0, accI1); accI1 = fma2(v1.y, wd1, accI1);
            accI2 = fma2(v2.x, wd0, accI2); accI2 = fma2(v2.y, wd1, accI2);
            accI3 = fma2(v3.x, wd0, accI3); accI3 = fma2(v3.y, wd1, accI3);
        }
        // agg part: staged features 32..191 -> rows 32+fa (I), 192+fa (amp), 352+fa (att)
#pragma unroll 4
        for (int f2 = 0; f2 < 80; f2++) {
            int fa = 2 * f2;
            int fs = 32 + fa;
            ulonglong2 v0 = *(const ulonglong2*)&st2[w][0][fs];
            ulonglong2 v1 = *(const ulonglong2*)&st2[w][1][fs];
            ulonglong2 v2 = *(const ulonglong2*)&st2[w][2][fs];
            ulonglong2 v3 = *(const ulonglong2*)&st2[w][3][fs];
            float wi0 = w1[(32 + fa) * FIN + g],  wi1 = w1[(33 + fa) * FIN + g];
            float wa0 = w1[(192 + fa) * FIN + g], wa1 = w1[(193 + fa) * FIN + g];
            float wt0 = w1[(352 + fa) * FIN + g], wt1 = w1[(353 + fa) * FIN + g];
            ull wdi0 = packf2(wi0, wi0), wdi1 = packf2(wi1, wi1);
            ull wda0 = packf2(wa0, wa0), wda1 = packf2(wa1, wa1);
            ull wdt0 = packf2(wt0, wt0), wdt1 = packf2(wt1, wt1);
            accI0 = fma2(v0.x, wdi0, accI0); accI0 = fma2(v0.y, wdi1, accI0);
            accI1 = fma2(v1.x, wdi0, accI1); accI1 = fma2(v1.y, wdi1, accI1);
            accI2 = fma2(v2.x, wdi0, accI2); accI2 = fma2(v2.y, wdi1, accI2);
            accI3 = fma2(v3.x, wdi0, accI3); accI3 = fma2(v3.y, wdi1, accI3);
            accA0 = fma2(v0.x, wda0, accA0); accA0 = fma2(v0.y, wda1, accA0);
            accA1 = fma2(v1.x, wda0, accA1); accA1 = fma2(v1.y, wda1, accA1);
            accA2 = fma2(v2.x, wda0, accA2); accA2 = fma2(v2.y, wda1, accA2);
            accA3 = fma2(v3.x, wda0, accA3); accA3 = fma2(v3.y, wda1, accA3);
            accT0 = fma2(v0.x, wdt0, accT0); accT0 = fma2(v0.y, wdt1, accT0);
            accT1 = fma2(v1.x, wdt0, accT1); accT1 = fma2(v1.y, wdt1, accT1);
            accT2 = fma2(v2.x, wdt0, accT2); accT2 = fma2(v2.y, wdt1, accT2);
            accT3 = fma2(v3.x, wdt0, accT3); accT3 = fma2(v3.y, wdt1, accT3);
        }
        // combine: acc = accI + s1*accA + s2*accT  (per pair: lo=node p, hi=node p+4)
        ull s1p0 = packf2(s1s[w][0], s1s[w][4]), s2p0 = packf2(s2s[w][0], s2s[w][4]);
        ull s1p1 = packf2(s1s[w][1], s1s[w][5]), s2p1 = packf2(s2s[w][1], s2s[w][5]);
        ull s1p2 = packf2(s1s[w][2], s1s[w][6]), s2p2 = packf2(s2s[w][2], s2s[w][6]);
        ull s1p3 = packf2(s1s[w][3], s1s[w][7]), s2p3 = packf2(s2s[w][3], s2s[w][7]);
        ull acc0 = fma2(accA0, s1p0, accI0); acc0 = fma2(accT0, s2p0, acc0);
        ull acc1 = fma2(accA1, s1p1, accI1); acc1 = fma2(accT1, s2p1, acc1);
        ull acc2 = fma2(accA2, s1p2, accI2); acc2 = fma2(accT2, s2p2, acc2);
        ull acc3 = fma2(accA3, s1p3, accI3); acc3 = fma2(accT3, s2p3, acc3);

        float m0, m1, m2, m3, m4, m5, m6, m7;
        unpackf2(acc0, m0, m4); unpackf2(acc1, m1, m5);
        unpackf2(acc2, m2, m6); unpackf2(acc3, m3, m7);
        m0 = fmaxf(m0, 0.f); m1 = fmaxf(m1, 0.f); m2 = fmaxf(m2, 0.f); m3 = fmaxf(m3, 0.f);
        m4 = fmaxf(m4, 0.f); m5 = fmaxf(m5, 0.f); m6 = fmaxf(m6, 0.f); m7 = fmaxf(m7, 0.f);
        float o0 = b2v, o1 = b2v, o2 = b2v, o3 = b2v;
        float o4 = b2v, o5 = b2v, o6 = b2v, o7 = b2v;
#pragma unroll
        for (int f = 0; f < FIN; f++) {
            float wv = w2v[f];
            o0 += __shfl_sync(FULLM, m0, f) * wv;
            o1 += __shfl_sync(FULLM, m1, f) * wv;
            o2 += __shfl_sync(FULLM, m2, f) * wv;
            o3 += __shfl_sync(FULLM, m3, f) * wv;
            o4 += __shfl_sync(FULLM, m4, f) * wv;
            o5 += __shfl_sync(FULLM, m5, f) * wv;
            o6 += __shfl_sync(FULLM, m6, f) * wv;
            o7 += __shfl_sync(FULLM, m7, f) * wv;
        }
        float oo[8] = {o0, o1, o2, o3, o4, o5, o6, o7};
#pragma unroll
        for (int j = 0; j < 8; j++) {
            int n = n0 + j;
            if (n < N) g_y[n * H + t * FIN + g] = oo[j];
        }
        __syncwarp();
    }
}

// ---------------- final linear + LayerNorm + ReLU residual ----------------
__global__ void __launch_bounds__(128) k_final(
    const float* __restrict__ atom_x,
    const float* __restrict__ lin_w, const float* __restrict__ lin_b,
    const float* __restrict__ ln_g, const float* __restrict__ ln_b,
    float* __restrict__ out, int N) {
    const int o = threadIdx.x;
    const int wid = o >> 5, l = o & 31;
    __shared__ __align__(16) float sy[4][H];
    __shared__ float red_s[4][4], red_q[4][4];
    const float lb = lin_b[o], gamma = ln_g[o], beta = ln_b[o];

    for (int grp = 0; grp < 4; grp++) {
        int n0 = blockIdx.x * 16 + grp * 4;
        __syncthreads();
#pragma unroll
        for (int j = 0; j < 4; j++) {
            int n = min(n0 + j, N - 1);
            sy[j][o] = g_y[n * H + o];
        }
        __syncthreads();
        const float4* y0 = (const float4*)sy[0];
        const float4* y1 = (const float4*)sy[1];
        const float4* y2 = (const float4*)sy[2];
        const float4* y3 = (const float4*)sy[3];
        float a0 = lb, a1 = lb, a2 = lb, a3 = lb;
#pragma unroll 4
        for (int kk = 0; kk < 32; kk++) {
            float4 v0 = y0[kk], v1 = y1[kk], v2 = y2[kk], v3 = y3[kk];
#pragma unroll
            for (int c = 0; c < 4; c++) {
                float wv = lin_w[(4 * kk + c) * H + o];
                a0 += ((const float*)&v0)[c] * wv;
                a1 += ((const float*)&v1)[c] * wv;
                a2 += ((const float*)&v2)[c] * wv;
                a3 += ((const float*)&v3)[c] * wv;
            }
        }
        float acc[4] = {a0, a1, a2, a3};
#pragma unroll
        for (int j = 0; j < 4; j++) {
            float s = acc[j], q = acc[j] * acc[j];
#pragma unroll
            for (int off = 16; off > 0; off >>= 1) {
                s += __shfl_xor_sync(FULLM, s, off);
                q += __shfl_xor_sync(FULLM, q, off);
            }
            if (l == 0) { red_s[j][wid] = s; red_q[j][wid] = q; }
        }
        __syncthreads();
#pragma unroll
        for (int j = 0; j < 4; j++) {
            int n = n0 + j;
            if (n >= N) continue;
            float s = red_s[j][0] + red_s[j][1] + red_s[j][2] + red_s[j][3];
            float q = red_q[j][0] + red_q[j][1] + red_q[j][2] + red_q[j][3];
            float mu = s * (1.f / 128.f);
            float var = q * (1.f / 128.f) - mu * mu;
            float v = (acc[j] - mu) * rsqrtf(var + 1e-5f) * gamma + beta;
            out[n * H + o] = atom_x[n * H + o] + fmaxf(v, 0.f);
        }
    }
}

// ---------------- launch ----------------
extern "C" void kernel_launch(void* const* d_in, const int* in_sizes, int n_in,
                              void* d_out, int out_size) {
    const float* atom_x  = (const float*)d_in[0];
    const int*   bond_x  = (const int*)d_in[1];
    const int*   edge_ix = (const int*)d_in[2];
    const int*   mol_deg = (const int*)d_in[3];
    const float* bond_emb = (const float*)d_in[4];
    const float* enc_w   = (const float*)d_in[5];
    const float* enc_b   = (const float*)d_in[6];
    const float* pre_w1  = (const float*)d_in[7];
    const float* pre_b1  = (const float*)d_in[8];
    const float* pre_w2  = (const float*)d_in[9];
    const float* pre_b2  = (const float*)d_in[10];
    const float* post_w1 = (const float*)d_in[11];
    const float* post_b1 = (const float*)d_in[12];
    const float* post_w2 = (const float*)d_in[13];
    const float* post_b2 = (const float*)d_in[14];
    const float* lin_w   = (const float*)d_in[15];
    const float* lin_b   = (const float*)d_in[16];
    const float* ln_g    = (const float*)d_in[17];
    const float* ln_b    = (const float*)d_in[18];
    float* out = (float*)d_out;

    int N = in_sizes[0] / H;
    int E = in_sizes[1];
    const int* src = edge_ix;
    const int* dst = edge_ix + E;

    k_setup<<<NB, 256>>>(dst, src, bond_x, atom_x, pre_w1, pre_b1, N, E);  // 0
    k_scalars<<<1, 256>>>(mol_deg, bond_emb, enc_w, enc_b);                // 1
    k_agg<<<1184, 128>>>(pre_w1, pre_w2, pre_b2, N);                       // 2
    k_post<<<dim3((N + 63) / 64, T), 128>>>(atom_x, post_w1, post_b1, post_w2, post_b2, N);  // 3 <- ncu
    k_final<<<(N + 15) / 16, 128>>>(atom_x, lin_w, lin_b, ln_g, ln_b, out, N);               // 4
}

// round 7
// speedup vs baseline: 1.1691x; 1.1691x over previous
#include <cuda_runtime.h>
#include <math.h>
#include <float.h>

#define NMAX 20000
#define EMAX 320000
#define H 128
#define T 4
#define FIN 32
#define FULLM 0xffffffffu
#define NB 132   // resident blocks for fused setup

typedef unsigned long long ull;

// ---------------- f32x2 packed helpers ----------------
__device__ __forceinline__ ull packf2(float lo, float hi) {
    ull r;
    asm("mov.b64 %0, {%1, %2};" : "=l"(r) : "r"(__float_as_uint(lo)), "r"(__float_as_uint(hi)));
    return r;
}
__device__ __forceinline__ void unpackf2(ull v, float& lo, float& hi) {
    unsigned int a, b;
    asm("mov.b64 {%0, %1}, %2;" : "=r"(a), "=r"(b) : "l"(v));
    lo = __uint_as_float(a); hi = __uint_as_float(b);
}
__device__ __forceinline__ ull fma2(ull a, ull b, ull c) {
    ull d;
    asm("fma.rn.f32x2 %0, %1, %2, %3;" : "=l"(d) : "l"(a), "l"(b), "l"(c));
    return d;
}
__device__ __forceinline__ ull add2(ull a, ull b) {
    ull d;
    asm("add.rn.f32x2 %0, %1, %2;" : "=l"(d) : "l"(a), "l"(b));
    return d;
}

// ---------------- device scratch ----------------
__device__ float g_avg_log;
__device__ float g_enc[5 * FIN];
__device__ int   g_deg[NMAX];
__device__ int   g_off[NMAX + 1];
__device__ int   g_fill[NMAX];
__device__ int   g_csr[EMAX];                 // packed: src | (bond<<27)
__device__ int   g_part[NB];
__device__ int   g_poff[NB];
__device__ float g_a0[(size_t)NMAX * H];
__device__ float g_p [(size_t)NMAX * H];
__device__ float g_agg[(size_t)NMAX * T * 5 * FIN];
__device__ float g_y[(size_t)NMAX * H];
__device__ unsigned int g_bar;
__device__ unsigned int g_done;

// ---------------- fused setup: zero + hist + PRE + scan + scatter ----------------
__device__ __forceinline__ void grid_bar(unsigned target) {
    __syncthreads();
    if (threadIdx.x == 0) {
        __threadfence();
        atomicAdd(&g_bar, 1u);
        while (*((volatile unsigned int*)&g_bar) < target) { }
        __threadfence();
    }
    __syncthreads();
}

__global__ void __launch_bounds__(256) k_setup(
    const int* __restrict__ dst, const int* __restrict__ src,
    const int* __restrict__ bond,
    const float* __restrict__ atom_x,
    const float* __restrict__ pre_w1, const float* __restrict__ pre_b1,
    int N, int E) {
    const int tid = threadIdx.x, b = blockIdx.x;
    const int gsz = NB * 256;
    const int gid = b * 256 + tid;
    __shared__ int sh[256];

    // P0: zero degree counters
    for (int i = gid; i < N; i += gsz) __stcg(&g_deg[i], 0);
    grid_bar(NB * 1);

    // P1: degree histogram
    for (int e = gid; e < E; e += gsz) atomicAdd(&g_deg[__ldg(&dst[e])], 1);

    // PRE (independent of hist): A0 = b1 + W1a.x, P = W1b.x
    {
        const int l = tid & 31;
        const int w = tid >> 5;
        const int t = w & 3;
        float w1a[FIN], w1b[FIN];
#pragma unroll
        for (int f = 0; f < FIN; f++) w1a[f] = pre_w1[(t * 96 + f) * FIN + l];
#pragma unroll
        for (int f = 0; f < FIN; f++) w1b[f] = pre_w1[(t * 96 + 32 + f) * FIN + l];
        const float b1 = pre_b1[t * FIN + l];
        for (int n = b * 2 + (w >> 2); n < N; n += NB * 2) {
            float x = atom_x[n * H + t * FIN + l];
            float a0 = b1, p = 0.f;
#pragma unroll
            for (int f = 0; f < FIN; f++) {
                float xf = __shfl_sync(FULLM, x, f);
                a0 += xf * w1a[f];
                p  += xf * w1b[f];
            }
            g_a0[n * H + t * FIN + l] = a0;
            g_p [n * H + t * FIN + l] = p;
        }
    }
    grid_bar(NB * 2);

    // P2: per-block chunk scan (chunk <= 256)
    const int chunk = (N + NB - 1) / NB;
    const int i = b * chunk + tid;
    int v = (tid < chunk && i < N) ? __ldcg(&g_deg[i]) : 0;
    sh[tid] = v;
    __syncthreads();
    for (int off = 1; off < 256; off <<= 1) {
        int tv = (tid >= off) ? sh[tid - off] : 0;
        __syncthreads();
        sh[tid] += tv;
        __syncthreads();
    }
    int local_excl = sh[tid] - v;
    if (tid == 255) __stcg(&g_part[b], sh[255]);
    grid_bar(NB * 3);

    // P3: block 0 scans block totals
    if (b == 0) {
        int v2 = (tid < NB) ? __ldcg(&g_part[tid]) : 0;
        sh[tid] = v2;
        __syncthreads();
        for (int off = 1; off < 256; off <<= 1) {
            int tv = (tid >= off) ? sh[tid - off] : 0;
            __syncthreads();
            sh[tid] += tv;
            __syncthreads();
        }
        if (tid < NB) __stcg(&g_poff[tid], sh[tid] - v2);
        if (tid == 0) __stcg(&g_off[N], E);
    }
    grid_bar(NB * 4);

    // P4: finalize offsets
    {
        int po = __ldcg(&g_poff[b]);
        if (tid < chunk && i < N) {
            int vv = local_excl + po;
            __stcg(&g_off[i], vv);
            __stcg(&g_fill[i], vv);
        }
    }
    grid_bar(NB * 5);

    // P5: scatter edges into CSR
    for (int e = gid; e < E; e += gsz) {
        int d = __ldg(&dst[e]);
        int p = atomicAdd(&g_fill[d], 1);
        __stcg(&g_csr[p], __ldg(&src[e]) | (__ldg(&bond[e]) << 27));
    }

    // reset barrier state for next graph replay
    __syncthreads();
    if (tid == 0) {
        if (atomicAdd(&g_done, 1u) == NB - 1) {
            atomicExch(&g_bar, 0u);
            atomicExch(&g_done, 0u);
        }
    }
}

// ---------------- scalars ----------------
__global__ void k_scalars(const int* __restrict__ mol_deg,
                          const float* __restrict__ bond_emb,
                          const float* __restrict__ enc_w,
                          const float* __restrict__ enc_b) {
    __shared__ float s_num[256], s_den[256];
    int tid = threadIdx.x;
    float num = 0.f, den = 0.f;
    if (tid < 128) {
        float d = (float)mol_deg[tid];
        num = logf((float)tid + 1.0f) * d;
        den = d;
    }
    s_num[tid] = num; s_den[tid] = den;
    __syncthreads();
    for (int off = 128; off > 0; off >>= 1) {
        if (tid < off) { s_num[tid] += s_num[tid + off]; s_den[tid] += s_den[tid + off]; }
        __syncthreads();
    }
    if (tid == 0) g_avg_log = s_num[0] / s_den[0];

    if (tid < 5 * FIN) {
        int b = tid >> 5, g = tid & 31;
        float a = enc_b[g];
        for (int k = 0; k < H; k++) a += bond_emb[b * H + k] * enc_w[k * FIN + g];
        g_enc[b * FIN + g] = a;
    }
}

// ---------------- edge loop: dual-node, edge-major staging, paired weights ----------------
__device__ __forceinline__ float dot_edge(const float* buf, const ull* w2d, float b2) {
    ull acc = 0ull;
#pragma unroll
    for (int j = 0; j < 8; j++) {
        ulonglong2 v = *(const ulonglong2*)&buf[4 * j];
        acc = fma2(v.x, w2d[2 * j], acc);
        acc = fma2(v.y, w2d[2 * j + 1], acc);
    }
    float lo, hi; unpackf2(acc, lo, hi);
    return lo + hi + b2;
}

__global__ void __launch_bounds__(128, 6) k_agg(
    const float* __restrict__ pre_w1,
    const float* __restrict__ pre_w2, const float* __restrict__ pre_b2, int N) {
    const int l = threadIdx.x & 31;
    const int t = threadIdx.x >> 5;
    __shared__ __align__(16) float rs[4][2][4][32];   // [warp][parity][edge-slot][feature]

    ull w2d[16];
#pragma unroll
    for (int j = 0; j < 16; j++)
        w2d[j] = packf2(pre_w2[(t * FIN + 2 * j) * FIN + l],
                        pre_w2[(t * FIN + 2 * j + 1) * FIN + l]);
    const float b2 = pre_b2[t * FIN + l];

    float evc0, evc1, evc2, evc3, evc4;
    {
        float w1c[FIN];
#pragma unroll
        for (int f = 0; f < FIN; f++) w1c[f] = pre_w1[(t * 96 + 64 + f) * FIN + l];
        float ev[5];
#pragma unroll
        for (int b = 0; b < 5; b++) {
            float et = g_enc[b * FIN + l];
            float a = 0.f;
#pragma unroll
            for (int f = 0; f < FIN; f++) a += __shfl_sync(FULLM, et, f) * w1c[f];
            ev[b] = a;
        }
        evc0 = ev[0]; evc1 = ev[1]; evc2 = ev[2]; evc3 = ev[3]; evc4 = ev[4];
    }
    const int off = t * FIN + l;
    const int half = (N + 1) >> 1;

#define EVSEL(bb) ({ float _e = evc0; _e = ((bb)==1)?evc1:_e; _e = ((bb)==2)?evc2:_e; \
                     _e = ((bb)==3)?evc3:_e; _e = ((bb)==4)?evc4:_e; _e; })

    for (int n = blockIdx.x; n < half; n += gridDim.x) {
        const int nA = n, nB = n + half;
        const bool hasB = nB < N;
        float a0A = g_a0[nA * H + off];
        int e0A = g_off[nA], e1A = g_off[nA + 1];
        float a0B = 0.f; int e0B = 0, e1B = 0;
        if (hasB) { a0B = g_a0[nB * H + off]; e0B = g_off[nB]; e1B = g_off[nB + 1]; }
        const int cntA = e1A - e0A, cntB = e1B - e0B;
        const int pAcnt = cntA >> 1, pBcnt = cntB >> 1;
        const int np = max(pAcnt, pBcnt);

        float sA = 0.f, qA = 0.f, sB = 0.f, qB = 0.f;
        float minA = FLT_MAX, maxA = -FLT_MAX, minB = FLT_MAX, maxB = -FLT_MAX;

        float paA = 0.f, pbA = 0.f, paB = 0.f, pbB = 0.f;
        int baA = 0, bbA = 0, baB = 0, bbB = 0;
        if (pAcnt > 0) {
            int k0 = g_csr[e0A], k1 = g_csr[e0A + 1];
            baA = k0 >> 27; bbA = k1 >> 27;
            paA = g_p[(k0 & 0x07ffffff) * H + off];
            pbA = g_p[(k1 & 0x07ffffff) * H + off];
        }
        if (pBcnt > 0) {
            int k0 = g_csr[e0B], k1 = g_csr[e0B + 1];
            baB = k0 >> 27; bbB = k1 >> 27;
            paB = g_p[(k0 & 0x07ffffff) * H + off];
            pbB = g_p[(k1 & 0x07ffffff) * H + off];
        }

        for (int i = 0; i < np; i++) {
            const int par = i & 1;
            const bool dA = i < pAcnt, dB = i < pBcnt;
            if (dA) {
                rs[t][par][0][l] = fmaxf(a0A + EVSEL(baA) + paA, 0.f);
                rs[t][par][1][l] = fmaxf(a0A + EVSEL(bbA) + pbA, 0.f);
            }
            if (dB) {
                rs[t][par][2][l] = fmaxf(a0B + EVSEL(baB) + paB, 0.f);
                rs[t][par][3][l] = fmaxf(a0B + EVSEL(bbB) + pbB, 0.f);
            }
            if (i + 1 < pAcnt) {
                int idx = e0A + 2 * (i + 1);
                int k0 = g_csr[idx], k1 = g_csr[idx + 1];
                baA = k0 >> 27; bbA = k1 >> 27;
                paA = g_p[(k0 & 0x07ffffff) * H + off];
                pbA = g_p[(k1 & 0x07ffffff) * H + off];
            }
            if (i + 1 < pBcnt) {
                int idx = e0B + 2 * (i + 1);
                int k0 = g_csr[idx], k1 = g_csr[idx + 1];
                baB = k0 >> 27; bbB = k1 >> 27;
                paB = g_p[(k0 & 0x07ffffff) * H + off];
                pbB = g_p[(k1 & 0x07ffffff) * H + off];
            }
            __syncwarp();
            if (dA) {
                float m0 = dot_edge(rs[t][par][0], w2d, b2);
                float m1 = dot_edge(rs[t][par][1], w2d, b2);
                sA += m0 + m1;
                qA = fmaf(m0, m0, qA); qA = fmaf(m1, m1, qA);
                minA = fminf(minA, fminf(m0, m1));
                maxA = fmaxf(maxA, fmaxf(m0, m1));
            }
            if (dB) {
                float m0 = dot_edge(rs[t][par][2], w2d, b2);
                float m1 = dot_edge(rs[t][par][3], w2d, b2);
                sB += m0 + m1;
                qB = fmaf(m0, m0, qB); qB = fmaf(m1, m1, qB);
                minB = fminf(minB, fminf(m0, m1));
                maxB = fmaxf(maxB, fmaxf(m0, m1));
            }
        }

        const bool tA = (cntA & 1) != 0, tB = (cntB & 1) != 0;
        if (tA | tB) {
            const int par = np & 1;
            if (tA) {
                int k = g_csr[e1A - 1];
                float p = g_p[(k & 0x07ffffff) * H + off];
                rs[t][par][0][l] = fmaxf(a0A + EVSEL(k >> 27) + p, 0.f);
            }
            if (tB) {
                int k = g_csr[e1B - 1];
                float p = g_p[(k & 0x07ffffff) * H + off];
                rs[t][par][2][l] = fmaxf(a0B + EVSEL(k >> 27) + p, 0.f);
            }
            __syncwarp();
            if (tA) {
                float m0 = dot_edge(rs[t][par][0], w2d, b2);
                sA += m0; qA = fmaf(m0, m0, qA);
                minA = fminf(minA, m0); maxA = fmaxf(maxA, m0);
            }
            if (tB) {
                float m0 = dot_edge(rs[t][par][2], w2d, b2);
                sB += m0; qB = fmaf(m0, m0, qB);
                minB = fminf(minB, m0); maxB = fmaxf(maxB, m0);
            }
        }

        {
            float c1 = fmaxf((float)cntA, 1.f);
            float mean = sA / c1;
            float stdv = sqrtf(fmaxf(qA / c1 - mean * mean, 0.f) + 1e-5f);
            float mn = minA, mx = maxA;
            if (cntA == 0) { mn = 0.f; mx = 0.f; }
            float* o = g_agg + (size_t)(nA * T + t) * 5 * FIN + l;
            o[0 * FIN] = sA; o[1 * FIN] = mean; o[2 * FIN] = mn;
            o[3 * FIN] = mx; o[4 * FIN] = stdv;
        }
        if (hasB) {
            float c1 = fmaxf((float)cntB, 1.f);
            float mean = sB / c1;
            float stdv = sqrtf(fmaxf(qB / c1 - mean * mean, 0.f) + 1e-5f);
            float mn = minB, mx = maxB;
            if (cntB == 0) { mn = 0.f; mx = 0.f; }
            float* o = g_agg + (size_t)(nB * T + t) * 5 * FIN + l;
            o[0 * FIN] = sB; o[1 * FIN] = mean; o[2 * FIN] = mn;
            o[3 * FIN] = mx; o[4 * FIN] = stdv;
        }
    }
#undef EVSEL
}

// ---------------- post-MLP: K-split cooperative GEMM ----------------
// Block = 1 tower x 16 nodes. Stage 16x512 scaled features in SMEM (node-major).
// Warp w accumulates K-rows [w*128, w*128+128) for ALL 16 nodes (f32x2 over K),
// cross-warp reduce in SMEM, then layer-2 shfl-dot on 4 nodes/warp.
__global__ void __launch_bounds__(128, 5) k_post(
    const float* __restrict__ atom_x,
    const float* __restrict__ post_w1, const float* __restrict__ post_b1,
    const float* __restrict__ post_w2, const float* __restrict__ post_b2,
    int N) {
    const int t = blockIdx.y;
    const int w = threadIdx.x >> 5;
    const int g = threadIdx.x & 31;
    __shared__ __align__(16) float st[16][512];     // 32 KB
    __shared__ float red[4][16][32];                // 8 KB

    const float avg = g_avg_log;
    const float* w1 = post_w1 + (size_t)t * 512 * FIN;
    const int n0 = blockIdx.x * 16;

    // stage: warp w stages nodes 4w..4w+3
#pragma unroll
    for (int j2 = 0; j2 < 4; j2++) {
        const int j = w * 4 + j2;
        const int n = min(n0 + j, N - 1);
        int cnt = g_deg[n];
        float c1 = fmaxf((float)cnt, 1.f);
        float logd = logf(c1 + 1.f);
        float s1 = logd / avg, s2 = avg / logd;
        st[j][g] = atom_x[n * H + t * FIN + g];
        const float* ag = g_agg + (size_t)(n * T + t) * 5 * FIN;
#pragma unroll
        for (int a = 0; a < 5; a++) {
            float v = ag[a * FIN + g];
            st[j][32 + a * FIN + g] = v;
            st[j][192 + a * FIN + g] = v * s1;
            st[j][352 + a * FIN + g] = v * s2;
        }
    }
    __syncthreads();

    // compute: warp w covers K in [w*128, w*128+128)
    const float* wbase = w1 + (size_t)(w * 128) * FIN + g;
    const int fbase = w * 128;
    ull acc[16];
#pragma unroll
    for (int nd = 0; nd < 16; nd++) acc[nd] = 0ull;

#pragma unroll 2
    for (int fq = 0; fq < 32; fq++) {
        const int f = fbase + 4 * fq;
        float wv0 = wbase[(4 * fq + 0) * FIN];
        float wv1 = wbase[(4 * fq + 1) * FIN];
        float wv2 = wbase[(4 * fq + 2) * FIN];
        float wv3 = wbase[(4 * fq + 3) * FIN];
        ull wd0 = packf2(wv0, wv1);
        ull wd1 = packf2(wv2, wv3);
#pragma unroll
        for (int nd = 0; nd < 16; nd++) {
            ulonglong2 v = *(const ulonglong2*)&st[nd][f];
            acc[nd] = fma2(v.x, wd0, acc[nd]);
            acc[nd] = fma2(v.y, wd1, acc[nd]);
        }
    }
#pragma unroll
    for (int nd = 0; nd < 16; nd++) {
        float lo, hi; unpackf2(acc[nd], lo, hi);
        red[w][nd][g] = lo + hi;
    }
    __syncthreads();

    // epilogue: warp w finishes nodes 4w..4w+3
    const float b1 = post_b1[t * FIN + g];
    const float b2v = post_b2[t * FIN + g];
    float m0, m1, m2, m3;
    {
        const int j = w * 4;
        m0 = fmaxf(red[0][j+0][g] + red[1][j+0][g] + red[2][j+0][g] + red[3][j+0][g] + b1, 0.f);
        m1 = fmaxf(red[0][j+1][g] + red[1][j+1][g] + red[2][j+1][g] + red[3][j+1][g] + b1, 0.f);
        m2 = fmaxf(red[0][j+2][g] + red[1][j+2][g] + red[2][j+2][g] + red[3][j+2][g] + b1, 0.f);
        m3 = fmaxf(red[0][j+3][g] + red[1][j+3][g] + red[2][j+3][g] + red[3][j+3][g] + b1, 0.f);
    }
    float o0 = b2v, o1 = b2v, o2 = b2v, o3 = b2v;
#pragma unroll
    for (int f = 0; f < FIN; f++) {
        float wv = __ldg(&post_w2[(t * FIN + f) * FIN + g]);
        o0 += __shfl_sync(FULLM, m0, f) * wv;
        o1 += __shfl_sync(FULLM, m1, f) * wv;
        o2 += __shfl_sync(FULLM, m2, f) * wv;
        o3 += __shfl_sync(FULLM, m3, f) * wv;
    }
    float oo[4] = {o0, o1, o2, o3};
#pragma unroll
    for (int j2 = 0; j2 < 4; j2++) {
        int n = n0 + w * 4 + j2;
        if (n < N) g_y[n * H + t * FIN + g] = oo[j2];
    }
}

// ---------------- final linear + LayerNorm + ReLU residual ----------------
__global__ void __launch_bounds__(128) k_final(
    const float* __restrict__ atom_x,
    const float* __restrict__ lin_w, const float* __restrict__ lin_b,
    const float* __restrict__ ln_g, const float* __restrict__ ln_b,
    float* __restrict__ out, int N) {
    const int o = threadIdx.x;
    const int wid = o >> 5, l = o & 31;
    __shared__ __align__(16) float sy[4][H];
    __shared__ float red_s[4][4], red_q[4][4];
    const float lb = lin_b[o], gamma = ln_g[o], beta = ln_b[o];

    for (int grp = 0; grp < 4; grp++) {
        int n0 = blockIdx.x * 16 + grp * 4;
        __syncthreads();
#pragma unroll
        for (int j = 0; j < 4; j++) {
            int n = min(n0 + j, N - 1);
            sy[j][o] = g_y[n * H + o];
        }
        __syncthreads();
        const float4* y0 = (const float4*)sy[0];
        const float4* y1 = (const float4*)sy[1];
        const float4* y2 = (const float4*)sy[2];
        const float4* y3 = (const float4*)sy[3];
        float a0 = lb, a1 = lb, a2 = lb, a3 = lb;
#pragma unroll 4
        for (int kk = 0; kk < 32; kk++) {
            float4 v0 = y0[kk], v1 = y1[kk], v2 = y2[kk], v3 = y3[kk];
#pragma unroll
            for (int c = 0; c < 4; c++) {
                float wv = lin_w[(4 * kk + c) * H + o];
                a0 += ((const float*)&v0)[c] * wv;
                a1 += ((const float*)&v1)[c] * wv;
                a2 += ((const float*)&v2)[c] * wv;
                a3 += ((const float*)&v3)[c] * wv;
            }
        }
        float acc[4] = {a0, a1, a2, a3};
#pragma unroll
        for (int j = 0; j < 4; j++) {
            float s = acc[j], q = acc[j] * acc[j];
#pragma unroll
            for (int off = 16; off > 0; off >>= 1) {
                s += __shfl_xor_sync(FULLM, s, off);
                q += __shfl_xor_sync(FULLM, q, off);
            }
            if (l == 0) { red_s[j][wid] = s; red_q[j][wid] = q; }
        }
        __syncthreads();
#pragma unroll
        for (int j = 0; j < 4; j++) {
            int n = n0 + j;
            if (n >= N) continue;
            float s = red_s[j][0] + red_s[j][1] + red_s[j][2] + red_s[j][3];
            float q = red_q[j][0] + red_q[j][1] + red_q[j][2] + red_q[j][3];
            float mu = s * (1.f / 128.f);
            float var = q * (1.f / 128.f) - mu * mu;
            float v = (acc[j] - mu) * rsqrtf(var + 1e-5f) * gamma + beta;
            out[n * H + o] = atom_x[n * H + o] + fmaxf(v, 0.f);
        }
    }
}

// ---------------- launch ----------------
extern "C" void kernel_launch(void* const* d_in, const int* in_sizes, int n_in,
                              void* d_out, int out_size) {
    const float* atom_x  = (const float*)d_in[0];
    const int*   bond_x  = (const int*)d_in[1];
    const int*   edge_ix = (const int*)d_in[2];
    const int*   mol_deg = (const int*)d_in[3];
    const float* bond_emb = (const float*)d_in[4];
    const float* enc_w   = (const float*)d_in[5];
    const float* enc_b   = (const float*)d_in[6];
    const float* pre_w1  = (const float*)d_in[7];
    const float* pre_b1  = (const float*)d_in[8];
    const float* pre_w2  = (const float*)d_in[9];
    const float* pre_b2  = (const float*)d_in[10];
    const float* post_w1 = (const float*)d_in[11];
    const float* post_b1 = (const float*)d_in[12];
    const float* post_w2 = (const float*)d_in[13];
    const float* post_b2 = (const float*)d_in[14];
    const float* lin_w   = (const float*)d_in[15];
    const float* lin_b   = (const float*)d_in[16];
    const float* ln_g    = (const float*)d_in[17];
    const float* ln_b    = (const float*)d_in[18];
    float* out = (float*)d_out;

    int N = in_sizes[0] / H;
    int E = in_sizes[1];
    const int* src = edge_ix;
    const int* dst = edge_ix + E;

    k_setup<<<NB, 256>>>(dst, src, bond_x, atom_x, pre_w1, pre_b1, N, E);  // 0
    k_scalars<<<1, 256>>>(mol_deg, bond_emb, enc_w, enc_b);                // 1
    k_agg<<<1184, 128>>>(pre_w1, pre_w2, pre_b2, N);                       // 2
    k_post<<<dim3((N + 15) / 16, T), 128>>>(atom_x, post_w1, post_b1, post_w2, post_b2, N);  // 3 <- ncu
    k_final<<<(N + 15) / 16, 128>>>(atom_x, lin_w, lin_b, ln_g, ln_b, out, N);               // 4
}

// round 8
// speedup vs baseline: 1.2998x; 1.1119x over previous
#include <cuda_runtime.h>
#include <math.h>
#include <float.h>

#define NMAX 20000
#define EMAX 320000
#define H 128
#define T 4
#define FIN 32
#define FULLM 0xffffffffu
#define NB 132   // resident blocks for fused setup

typedef unsigned long long ull;

// ---------------- f32x2 packed helpers ----------------
__device__ __forceinline__ ull packf2(float lo, float hi) {
    ull r;
    asm("mov.b64 %0, {%1, %2};" : "=l"(r) : "r"(__float_as_uint(lo)), "r"(__float_as_uint(hi)));
    return r;
}
__device__ __forceinline__ void unpackf2(ull v, float& lo, float& hi) {
    unsigned int a, b;
    asm("mov.b64 {%0, %1}, %2;" : "=r"(a), "=r"(b) : "l"(v));
    lo = __uint_as_float(a); hi = __uint_as_float(b);
}
__device__ __forceinline__ ull fma2(ull a, ull b, ull c) {
    ull d;
    asm("fma.rn.f32x2 %0, %1, %2, %3;" : "=l"(d) : "l"(a), "l"(b), "l"(c));
    return d;
}
__device__ __forceinline__ ull add2(ull a, ull b) {
    ull d;
    asm("add.rn.f32x2 %0, %1, %2;" : "=l"(d) : "l"(a), "l"(b));
    return d;
}

// ---------------- device scratch ----------------
__device__ float g_avg_log;
__device__ float g_enc[5 * FIN];
__device__ int   g_deg[NMAX];
__device__ int   g_off[NMAX + 1];
__device__ int   g_fill[NMAX];
__device__ int   g_csr[EMAX];                 // packed: (src*H) | (bond<<27)
__device__ int   g_part[NB];
__device__ int   g_poff[NB];
__device__ float g_a0[(size_t)NMAX * H];
__device__ float g_p [(size_t)NMAX * H];
__device__ float g_agg[(size_t)NMAX * T * 5 * FIN];
__device__ float g_y[(size_t)NMAX * H];
__device__ unsigned int g_bar;
__device__ unsigned int g_done;

// ---------------- fused setup: zero + hist + PRE + SCALARS + scan + scatter ----------------
__device__ __forceinline__ void grid_bar(unsigned target) {
    __syncthreads();
    if (threadIdx.x == 0) {
        __threadfence();
        atomicAdd(&g_bar, 1u);
        while (*((volatile unsigned int*)&g_bar) < target) { }
        __threadfence();
    }
    __syncthreads();
}

__global__ void __launch_bounds__(256) k_setup(
    const int* __restrict__ dst, const int* __restrict__ src,
    const int* __restrict__ bond,
    const float* __restrict__ atom_x,
    const float* __restrict__ pre_w1, const float* __restrict__ pre_b1,
    const int* __restrict__ mol_deg,
    const float* __restrict__ bond_emb,
    const float* __restrict__ enc_w, const float* __restrict__ enc_b,
    int N, int E) {
    const int tid = threadIdx.x, b = blockIdx.x;
    const int gsz = NB * 256;
    const int gid = b * 256 + tid;
    __shared__ int sh[256];
    __shared__ float sf[256], sf2[256];

    // P0: zero degree counters
    for (int i = gid; i < N; i += gsz) __stcg(&g_deg[i], 0);
    grid_bar(NB * 1);

    // P1: degree histogram
    for (int e = gid; e < E; e += gsz) atomicAdd(&g_deg[__ldg(&dst[e])], 1);

    // SCALARS (block 1, independent of hist): avg_log + bond-encode table
    if (b == 1) {
        float num = 0.f, den = 0.f;
        if (tid < 128) {
            float d = (float)mol_deg[tid];
            num = logf((float)tid + 1.0f) * d;
            den = d;
        }
        sf[tid] = num; sf2[tid] = den;
        __syncthreads();
        for (int off = 128; off > 0; off >>= 1) {
            if (tid < off) { sf[tid] += sf[tid + off]; sf2[tid] += sf2[tid + off]; }
            __syncthreads();
        }
        if (tid == 0) g_avg_log = sf[0] / sf2[0];
        if (tid < 5 * FIN) {
            int bb = tid >> 5, g = tid & 31;
            float a = enc_b[g];
            for (int k = 0; k < H; k++) a += bond_emb[bb * H + k] * enc_w[k * FIN + g];
            g_enc[bb * FIN + g] = a;
        }
        __syncthreads();
    }

    // PRE (independent of hist): A0 = b1 + W1a.x, P = W1b.x
    {
        const int l = tid & 31;
        const int w = tid >> 5;
        const int t = w & 3;
        float w1a[FIN], w1b[FIN];
#pragma unroll
        for (int f = 0; f < FIN; f++) w1a[f] = pre_w1[(t * 96 + f) * FIN + l];
#pragma unroll
        for (int f = 0; f < FIN; f++) w1b[f] = pre_w1[(t * 96 + 32 + f) * FIN + l];
        const float b1 = pre_b1[t * FIN + l];
        for (int n = b * 2 + (w >> 2); n < N; n += NB * 2) {
            float x = atom_x[n * H + t * FIN + l];
            float a0 = b1, p = 0.f;
#pragma unroll
            for (int f = 0; f < FIN; f++) {
                float xf = __shfl_sync(FULLM, x, f);
                a0 += xf * w1a[f];
                p  += xf * w1b[f];
            }
            g_a0[n * H + t * FIN + l] = a0;
            g_p [n * H + t * FIN + l] = p;
        }
    }
    grid_bar(NB * 2);

    // P2: per-block chunk scan (chunk <= 256)
    const int chunk = (N + NB - 1) / NB;
    const int i = b * chunk + tid;
    int v = (tid < chunk && i < N) ? __ldcg(&g_deg[i]) : 0;
    sh[tid] = v;
    __syncthreads();
    for (int off = 1; off < 256; off <<= 1) {
        int tv = (tid >= off) ? sh[tid - off] : 0;
        __syncthreads();
        sh[tid] += tv;
        __syncthreads();
    }
    int local_excl = sh[tid] - v;
    if (tid == 255) __stcg(&g_part[b], sh[255]);
    grid_bar(NB * 3);

    // P3: block 0 scans block totals
    if (b == 0) {
        int v2 = (tid < NB) ? __ldcg(&g_part[tid]) : 0;
        sh[tid] = v2;
        __syncthreads();
        for (int off = 1; off < 256; off <<= 1) {
            int tv = (tid >= off) ? sh[tid - off] : 0;
            __syncthreads();
            sh[tid] += tv;
            __syncthreads();
        }
        if (tid < NB) __stcg(&g_poff[tid], sh[tid] - v2);
        if (tid == 0) __stcg(&g_off[N], E);
    }
    grid_bar(NB * 4);

    // P4: finalize offsets
    {
        int po = __ldcg(&g_poff[b]);
        if (tid < chunk && i < N) {
            int vv = local_excl + po;
            __stcg(&g_off[i], vv);
            __stcg(&g_fill[i], vv);
        }
    }
    grid_bar(NB * 5);

    // P5: scatter edges into CSR (src pre-multiplied by H)
    for (int e = gid; e < E; e += gsz) {
        int d = __ldg(&dst[e]);
        int p = atomicAdd(&g_fill[d], 1);
        __stcg(&g_csr[p], (__ldg(&src[e]) * H) | (__ldg(&bond[e]) << 27));
    }

    // reset barrier state for next graph replay
    __syncthreads();
    if (tid == 0) {
        if (atomicAdd(&g_done, 1u) == NB - 1) {
            atomicExch(&g_bar, 0u);
            atomicExch(&g_done, 0u);
        }
    }
}

// ---------------- edge loop: dual-node, edge-major staging, paired weights ----------------
__device__ __forceinline__ float dot_edge(const float* buf, const ull* w2d, float b2) {
    ull acc = 0ull;
#pragma unroll
    for (int j = 0; j < 8; j++) {
        ulonglong2 v = *(const ulonglong2*)&buf[4 * j];
        acc = fma2(v.x, w2d[2 * j], acc);
        acc = fma2(v.y, w2d[2 * j + 1], acc);
    }
    float lo, hi; unpackf2(acc, lo, hi);
    return lo + hi + b2;
}

__global__ void __launch_bounds__(128, 6) k_agg(
    const float* __restrict__ pre_w1,
    const float* __restrict__ pre_w2, const float* __restrict__ pre_b2, int N) {
    const int l = threadIdx.x & 31;
    const int t = threadIdx.x >> 5;
    __shared__ __align__(16) float rs[4][2][4][32];   // [warp][parity][edge-slot][feature]

    ull w2d[16];
#pragma unroll
    for (int j = 0; j < 16; j++)
        w2d[j] = packf2(pre_w2[(t * FIN + 2 * j) * FIN + l],
                        pre_w2[(t * FIN + 2 * j + 1) * FIN + l]);
    const float b2 = pre_b2[t * FIN + l];

    float evc0, evc1, evc2, evc3, evc4;
    {
        float w1c[FIN];
#pragma unroll
        for (int f = 0; f < FIN; f++) w1c[f] = pre_w1[(t * 96 + 64 + f) * FIN + l];
        float ev[5];
#pragma unroll
        for (int b = 0; b < 5; b++) {
            float et = g_enc[b * FIN + l];
            float a = 0.f;
#pragma unroll
            for (int f = 0; f < FIN; f++) a += __shfl_sync(FULLM, et, f) * w1c[f];
            ev[b] = a;
        }
        evc0 = ev[0]; evc1 = ev[1]; evc2 = ev[2]; evc3 = ev[3]; evc4 = ev[4];
    }
    const int off = t * FIN + l;
    const int half = (N + 1) >> 1;

#define EVSEL(bb) ({ float _e = evc0; _e = ((bb)==1)?evc1:_e; _e = ((bb)==2)?evc2:_e; \
                     _e = ((bb)==3)?evc3:_e; _e = ((bb)==4)?evc4:_e; _e; })

    for (int n = blockIdx.x; n < half; n += gridDim.x) {
        const int nA = n, nB = n + half;
        const bool hasB = nB < N;
        float a0A = g_a0[nA * H + off];
        int e0A = g_off[nA], e1A = g_off[nA + 1];
        float a0B = 0.f; int e0B = 0, e1B = 0;
        if (hasB) { a0B = g_a0[nB * H + off]; e0B = g_off[nB]; e1B = g_off[nB + 1]; }
        const int cntA = e1A - e0A, cntB = e1B - e0B;
        const int pAcnt = cntA >> 1, pBcnt = cntB >> 1;
        const int np = max(pAcnt, pBcnt);

        float sA = 0.f, qA = 0.f, sB = 0.f, qB = 0.f;
        float minA = FLT_MAX, maxA = -FLT_MAX, minB = FLT_MAX, maxB = -FLT_MAX;

        float paA = 0.f, pbA = 0.f, paB = 0.f, pbB = 0.f;
        int baA = 0, bbA = 0, baB = 0, bbB = 0;
        if (pAcnt > 0) {
            int k0 = g_csr[e0A], k1 = g_csr[e0A + 1];
            baA = k0 >> 27; bbA = k1 >> 27;
            paA = g_p[(k0 & 0x07ffffff) + off];
            pbA = g_p[(k1 & 0x07ffffff) + off];
        }
        if (pBcnt > 0) {
            int k0 = g_csr[e0B], k1 = g_csr[e0B + 1];
            baB = k0 >> 27; bbB = k1 >> 27;
            paB = g_p[(k0 & 0x07ffffff) + off];
            pbB = g_p[(k1 & 0x07ffffff) + off];
        }

        for (int i = 0; i < np; i++) {
            const int par = i & 1;
            const bool dA = i < pAcnt, dB = i < pBcnt;
            if (dA) {
                rs[t][par][0][l] = fmaxf(a0A + EVSEL(baA) + paA, 0.f);
                rs[t][par][1][l] = fmaxf(a0A + EVSEL(bbA) + pbA, 0.f);
            }
            if (dB) {
                rs[t][par][2][l] = fmaxf(a0B + EVSEL(baB) + paB, 0.f);
                rs[t][par][3][l] = fmaxf(a0B + EVSEL(bbB) + pbB, 0.f);
            }
            if (i + 1 < pAcnt) {
                int idx = e0A + 2 * (i + 1);
                int k0 = g_csr[idx], k1 = g_csr[idx + 1];
                baA = k0 >> 27; bbA = k1 >> 27;
                paA = g_p[(k0 & 0x07ffffff) + off];
                pbA = g_p[(k1 & 0x07ffffff) + off];
            }
            if (i + 1 < pBcnt) {
                int idx = e0B + 2 * (i + 1);
                int k0 = g_csr[idx], k1 = g_csr[idx + 1];
                baB = k0 >> 27; bbB = k1 >> 27;
                paB = g_p[(k0 & 0x07ffffff) + off];
                pbB = g_p[(k1 & 0x07ffffff) + off];
            }
            __syncwarp();
            if (dA) {
                float m0 = dot_edge(rs[t][par][0], w2d, b2);
                float m1 = dot_edge(rs[t][par][1], w2d, b2);
                sA += m0 + m1;
                qA = fmaf(m0, m0, qA); qA = fmaf(m1, m1, qA);
                minA = fminf(minA, fminf(m0, m1));
                maxA = fmaxf(maxA, fmaxf(m0, m1));
            }
            if (dB) {
                float m0 = dot_edge(rs[t][par][2], w2d, b2);
                float m1 = dot_edge(rs[t][par][3], w2d, b2);
                sB += m0 + m1;
                qB = fmaf(m0, m0, qB); qB = fmaf(m1, m1, qB);
                minB = fminf(minB, fminf(m0, m1));
                maxB = fmaxf(maxB, fmaxf(m0, m1));
            }
        }

        const bool tA = (cntA & 1) != 0, tB = (cntB & 1) != 0;
        if (tA | tB) {
            const int par = np & 1;
            if (tA) {
                int k = g_csr[e1A - 1];
                float p = g_p[(k & 0x07ffffff) + off];
                rs[t][par][0][l] = fmaxf(a0A + EVSEL(k >> 27) + p, 0.f);
            }
            if (tB) {
                int k = g_csr[e1B - 1];
                float p = g_p[(k & 0x07ffffff) + off];
                rs[t][par][2][l] = fmaxf(a0B + EVSEL(k >> 27) + p, 0.f);
            }
            __syncwarp();
            if (tA) {
                float m0 = dot_edge(rs[t][par][0], w2d, b2);
                sA += m0; qA = fmaf(m0, m0, qA);
                minA = fminf(minA, m0); maxA = fmaxf(maxA, m0);
            }
            if (tB) {
                float m0 = dot_edge(rs[t][par][2], w2d, b2);
                sB += m0; qB = fmaf(m0, m0, qB);
                minB = fminf(minB, m0); maxB = fmaxf(maxB, m0);
            }
        }

        {
            float c1 = fmaxf((float)cntA, 1.f);
            float mean = sA / c1;
            float stdv = sqrtf(fmaxf(qA / c1 - mean * mean, 0.f) + 1e-5f);
            float mn = minA, mx = maxA;
            if (cntA == 0) { mn = 0.f; mx = 0.f; }
            float* o = g_agg + (size_t)(nA * T + t) * 5 * FIN + l;
            o[0 * FIN] = sA; o[1 * FIN] = mean; o[2 * FIN] = mn;
            o[3 * FIN] = mx; o[4 * FIN] = stdv;
        }
        if (hasB) {
            float c1 = fmaxf((float)cntB, 1.f);
            float mean = sB / c1;
            float stdv = sqrtf(fmaxf(qB / c1 - mean * mean, 0.f) + 1e-5f);
            float mn = minB, mx = maxB;
            if (cntB == 0) { mn = 0.f; mx = 0.f; }
            float* o = g_agg + (size_t)(nB * T + t) * 5 * FIN + l;
            o[0 * FIN] = sB; o[1 * FIN] = mean; o[2 * FIN] = mn;
            o[3 * FIN] = mx; o[4 * FIN] = stdv;
        }
    }
#undef EVSEL
}

// ---------------- post-MLP: K-split cooperative GEMM ----------------
__global__ void __launch_bounds__(128, 5) k_post(
    const float* __restrict__ atom_x,
    const float* __restrict__ post_w1, const float* __restrict__ post_b1,
    const float* __restrict__ post_w2, const float* __restrict__ post_b2,
    int N) {
    const int t = blockIdx.y;
    const int w = threadIdx.x >> 5;
    const int g = threadIdx.x & 31;
    __shared__ __align__(16) float st[16][512];     // 32 KB
    __shared__ float red[4][16][32];                // 8 KB

    const float avg = g_avg_log;
    const float* w1 = post_w1 + (size_t)t * 512 * FIN;
    const int n0 = blockIdx.x * 16;

    // stage: warp w stages nodes 4w..4w+3
#pragma unroll
    for (int j2 = 0; j2 < 4; j2++) {
        const int j = w * 4 + j2;
        const int n = min(n0 + j, N - 1);
        int cnt = g_deg[n];
        float c1 = fmaxf((float)cnt, 1.f);
        float logd = logf(c1 + 1.f);
        float s1 = logd / avg, s2 = avg / logd;
        st[j][g] = atom_x[n * H + t * FIN + g];
        const float* ag = g_agg + (size_t)(n * T + t) * 5 * FIN;
#pragma unroll
        for (int a = 0; a < 5; a++) {
            float v = ag[a * FIN + g];
            st[j][32 + a * FIN + g] = v;
            st[j][192 + a * FIN + g] = v * s1;
            st[j][352 + a * FIN + g] = v * s2;
        }
    }
    __syncthreads();

    // compute: warp w covers K in [w*128, w*128+128)
    const float* wbase = w1 + (size_t)(w * 128) * FIN + g;
    const int fbase = w * 128;
    ull acc[16];
#pragma unroll
    for (int nd = 0; nd < 16; nd++) acc[nd] = 0ull;

#pragma unroll 2
    for (int fq = 0; fq < 32; fq++) {
        const int f = fbase + 4 * fq;
        float wv0 = wbase[(4 * fq + 0) * FIN];
        float wv1 = wbase[(4 * fq + 1) * FIN];
        float wv2 = wbase[(4 * fq + 2) * FIN];
        float wv3 = wbase[(4 * fq + 3) * FIN];
        ull wd0 = packf2(wv0, wv1);
        ull wd1 = packf2(wv2, wv3);
#pragma unroll
        for (int nd = 0; nd < 16; nd++) {
            ulonglong2 v = *(const ulonglong2*)&st[nd][f];
            acc[nd] = fma2(v.x, wd0, acc[nd]);
            acc[nd] = fma2(v.y, wd1, acc[nd]);
        }
    }
#pragma unroll
    for (int nd = 0; nd < 16; nd++) {
        float lo, hi; unpackf2(acc[nd], lo, hi);
        red[w][nd][g] = lo + hi;
    }
    __syncthreads();

    // epilogue: warp w finishes nodes 4w..4w+3
    const float b1 = post_b1[t * FIN + g];
    const float b2v = post_b2[t * FIN + g];
    float m0, m1, m2, m3;
    {
        const int j = w * 4;
        m0 = fmaxf(red[0][j+0][g] + red[1][j+0][g] + red[2][j+0][g] + red[3][j+0][g] + b1, 0.f);
        m1 = fmaxf(red[0][j+1][g] + red[1][j+1][g] + red[2][j+1][g] + red[3][j+1][g] + b1, 0.f);
        m2 = fmaxf(red[0][j+2][g] + red[1][j+2][g] + red[2][j+2][g] + red[3][j+2][g] + b1, 0.f);
        m3 = fmaxf(red[0][j+3][g] + red[1][j+3][g] + red[2][j+3][g] + red[3][j+3][g] + b1, 0.f);
    }
    float o0 = b2v, o1 = b2v, o2 = b2v, o3 = b2v;
#pragma unroll
    for (int f = 0; f < FIN; f++) {
        float wv = __ldg(&post_w2[(t * FIN + f) * FIN + g]);
        o0 += __shfl_sync(FULLM, m0, f) * wv;
        o1 += __shfl_sync(FULLM, m1, f) * wv;
        o2 += __shfl_sync(FULLM, m2, f) * wv;
        o3 += __shfl_sync(FULLM, m3, f) * wv;
    }
    float oo[4] = {o0, o1, o2, o3};
#pragma unroll
    for (int j2 = 0; j2 < 4; j2++) {
        int n = n0 + w * 4 + j2;
        if (n < N) g_y[n * H + t * FIN + g] = oo[j2];
    }
}

// ---------------- final linear + LayerNorm + ReLU residual (f32x2 packed) ----------------
// Nodes j and j+2 packed into one f32x2 accumulator lane.
__global__ void __launch_bounds__(128) k_final(
    const float* __restrict__ atom_x,
    const float* __restrict__ lin_w, const float* __restrict__ lin_b,
    const float* __restrict__ ln_g, const float* __restrict__ ln_b,
    float* __restrict__ out, int N) {
    const int o = threadIdx.x;
    const int wid = o >> 5, l = o & 31;
    __shared__ __align__(16) float2 sy2[2][H];   // pair p: (node j, node j+2)
    __shared__ float red_s[4][4], red_q[4][4];
    const float lb = lin_b[o], gamma = ln_g[o], beta = ln_b[o];

    for (int grp = 0; grp < 4; grp++) {
        int n0 = blockIdx.x * 16 + grp * 4;
        __syncthreads();
        // stage: node j -> pair (j&1), half (j>>1)
#pragma unroll
        for (int j = 0; j < 4; j++) {
            int n = min(n0 + j, N - 1);
            ((float*)&sy2[j & 1][0])[2 * o + (j >> 1)] = g_y[n * H + o];
        }
        __syncthreads();
        ull a0 = packf2(lb, lb), a1 = a0;
#pragma unroll 4
        for (int kk = 0; kk < 64; kk++) {
            int k = 2 * kk;
            ulonglong2 v0 = *(const ulonglong2*)&sy2[0][k];
            ulonglong2 v1 = *(const ulonglong2*)&sy2[1][k];
            float wv0 = lin_w[k * H + o];
            float wv1 = lin_w[(k + 1) * H + o];
            ull wd0 = packf2(wv0, wv0), wd1 = packf2(wv1, wv1);
            a0 = fma2(v0.x, wd0, a0); a0 = fma2(v0.y, wd1, a0);
            a1 = fma2(v1.x, wd0, a1); a1 = fma2(v1.y, wd1, a1);
        }
        float acc[4];
        unpackf2(a0, acc[0], acc[2]);
        unpackf2(a1, acc[1], acc[3]);
#pragma unroll
        for (int j = 0; j < 4; j++) {
            float s = acc[j], q = acc[j] * acc[j];
#pragma unroll
            for (int off = 16; off > 0; off >>= 1) {
                s += __shfl_xor_sync(FULLM, s, off);
                q += __shfl_xor_sync(FULLM, q, off);
            }
            if (l == 0) { red_s[j][wid] = s; red_q[j][wid] = q; }
        }
        __syncthreads();
#pragma unroll
        for (int j = 0; j < 4; j++) {
            int n = n0 + j;
            if (n >= N) continue;
            float s = red_s[j][0] + red_s[j][1] + red_s[j][2] + red_s[j][3];
            float q = red_q[j][0] + red_q[j][1] + red_q[j][2] + red_q[j][3];
            float mu = s * (1.f / 128.f);
            float var = q * (1.f / 128.f) - mu * mu;
            float v = (acc[j] - mu) * rsqrtf(var + 1e-5f) * gamma + beta;
            out[n * H + o] = atom_x[n * H + o] + fmaxf(v, 0.f);
        }
    }
}

// ---------------- launch ----------------
extern "C" void kernel_launch(void* const* d_in, const int* in_sizes, int n_in,
                              void* d_out, int out_size) {
    const float* atom_x  = (const float*)d_in[0];
    const int*   bond_x  = (const int*)d_in[1];
    const int*   edge_ix = (const int*)d_in[2];
    const int*   mol_deg = (const int*)d_in[3];
    const float* bond_emb = (const float*)d_in[4];
    const float* enc_w   = (const float*)d_in[5];
    const float* enc_b   = (const float*)d_in[6];
    const float* pre_w1  = (const float*)d_in[7];
    const float* pre_b1  = (const float*)d_in[8];
    const float* pre_w2  = (const float*)d_in[9];
    const float* pre_b2  = (const float*)d_in[10];
    const float* post_w1 = (const float*)d_in[11];
    const float* post_b1 = (const float*)d_in[12];
    const float* post_w2 = (const float*)d_in[13];
    const float* post_b2 = (const float*)d_in[14];
    const float* lin_w   = (const float*)d_in[15];
    const float* lin_b   = (const float*)d_in[16];
    const float* ln_g    = (const float*)d_in[17];
    const float* ln_b    = (const float*)d_in[18];
    float* out = (float*)d_out;

    int N = in_sizes[0] / H;
    int E = in_sizes[1];
    const int* src = edge_ix;
    const int* dst = edge_ix + E;

    k_setup<<<NB, 256>>>(dst, src, bond_x, atom_x, pre_w1, pre_b1,
                         mol_deg, bond_emb, enc_w, enc_b, N, E);            // 0
    k_agg<<<888, 128>>>(pre_w1, pre_w2, pre_b2, N);                         // 1
    k_post<<<dim3((N + 15) / 16, T), 128>>>(atom_x, post_w1, post_b1, post_w2, post_b2, N);  // 2
    k_final<<<(N + 15) / 16, 128>>>(atom_x, lin_w, lin_b, ln_g, ln_b, out, N);               // 3 <- ncu
}

// round 9
// speedup vs baseline: 1.3852x; 1.0656x over previous
#include <cuda_runtime.h>
#include <math.h>
#include <float.h>

#define NMAX 20000
#define EMAX 320000
#define H 128
#define T 4
#define FIN 32
#define FULLM 0xffffffffu
#define NB 132   // resident blocks for fused setup

typedef unsigned long long ull;

// ---------------- f32x2 packed helpers ----------------
__device__ __forceinline__ ull packf2(float lo, float hi) {
    ull r;
    asm("mov.b64 %0, {%1, %2};" : "=l"(r) : "r"(__float_as_uint(lo)), "r"(__float_as_uint(hi)));
    return r;
}
__device__ __forceinline__ void unpackf2(ull v, float& lo, float& hi) {
    unsigned int a, b;
    asm("mov.b64 {%0, %1}, %2;" : "=r"(a), "=r"(b) : "l"(v));
    lo = __uint_as_float(a); hi = __uint_as_float(b);
}
__device__ __forceinline__ ull fma2(ull a, ull b, ull c) {
    ull d;
    asm("fma.rn.f32x2 %0, %1, %2, %3;" : "=l"(d) : "l"(a), "l"(b), "l"(c));
    return d;
}
__device__ __forceinline__ ull add2(ull a, ull b) {
    ull d;
    asm("add.rn.f32x2 %0, %1, %2;" : "=l"(d) : "l"(a), "l"(b));
    return d;
}

// ---------------- device scratch ----------------
__device__ float g_avg_log;
__device__ float g_enc[5 * FIN];
__device__ int   g_deg[NMAX];
__device__ int   g_off[NMAX + 1];
__device__ int   g_fill[NMAX];
__device__ int   g_csr[EMAX];                 // packed: (src*H) | (bond<<27)
__device__ int   g_part[NB];
__device__ int   g_poff[NB];
__device__ float g_a0[(size_t)NMAX * H];
__device__ float g_p [(size_t)NMAX * H];
__device__ float g_agg[(size_t)NMAX * T * 5 * FIN];
__device__ float g_y[(size_t)NMAX * H];
__device__ unsigned int g_bar;
__device__ unsigned int g_done;

// ---------------- fused setup: zero + hist + PRE + SCALARS + scan + scatter ----------------
__device__ __forceinline__ void grid_bar(unsigned target) {
    __syncthreads();
    if (threadIdx.x == 0) {
        __threadfence();
        atomicAdd(&g_bar, 1u);
        while (*((volatile unsigned int*)&g_bar) < target) { }
        __threadfence();
    }
    __syncthreads();
}

__global__ void __launch_bounds__(256) k_setup(
    const int* __restrict__ dst, const int* __restrict__ src,
    const int* __restrict__ bond,
    const float* __restrict__ atom_x,
    const float* __restrict__ pre_w1, const float* __restrict__ pre_b1,
    const int* __restrict__ mol_deg,
    const float* __restrict__ bond_emb,
    const float* __restrict__ enc_w, const float* __restrict__ enc_b,
    int N, int E) {
    const int tid = threadIdx.x, b = blockIdx.x;
    const int gsz = NB * 256;
    const int gid = b * 256 + tid;
    __shared__ int sh[256];
    __shared__ float sf[256], sf2[256];

    // P0: zero degree counters
    for (int i = gid; i < N; i += gsz) __stcg(&g_deg[i], 0);
    grid_bar(NB * 1);

    // P1: degree histogram
    for (int e = gid; e < E; e += gsz) atomicAdd(&g_deg[__ldg(&dst[e])], 1);

    // SCALARS (block 1, independent of hist): avg_log + bond-encode table
    if (b == 1) {
        float num = 0.f, den = 0.f;
        if (tid < 128) {
            float d = (float)mol_deg[tid];
            num = logf((float)tid + 1.0f) * d;
            den = d;
        }
        sf[tid] = num; sf2[tid] = den;
        __syncthreads();
        for (int off = 128; off > 0; off >>= 1) {
            if (tid < off) { sf[tid] += sf[tid + off]; sf2[tid] += sf2[tid + off]; }
            __syncthreads();
        }
        if (tid == 0) g_avg_log = sf[0] / sf2[0];
        if (tid < 5 * FIN) {
            int bb = tid >> 5, g = tid & 31;
            float a = enc_b[g];
            for (int k = 0; k < H; k++) a += bond_emb[bb * H + k] * enc_w[k * FIN + g];
            g_enc[bb * FIN + g] = a;
        }
        __syncthreads();
    }

    // PRE (independent of hist): A0 = b1 + W1a.x, P = W1b.x
    {
        const int l = tid & 31;
        const int w = tid >> 5;
        const int t = w & 3;
        float w1a[FIN], w1b[FIN];
#pragma unroll
        for (int f = 0; f < FIN; f++) w1a[f] = pre_w1[(t * 96 + f) * FIN + l];
#pragma unroll
        for (int f = 0; f < FIN; f++) w1b[f] = pre_w1[(t * 96 + 32 + f) * FIN + l];
        const float b1 = pre_b1[t * FIN + l];
        for (int n = b * 2 + (w >> 2); n < N; n += NB * 2) {
            float x = atom_x[n * H + t * FIN + l];
            float a0 = b1, p = 0.f;
#pragma unroll
            for (int f = 0; f < FIN; f++) {
                float xf = __shfl_sync(FULLM, x, f);
                a0 += xf * w1a[f];
                p  += xf * w1b[f];
            }
            g_a0[n * H + t * FIN + l] = a0;
            g_p [n * H + t * FIN + l] = p;
        }
    }
    grid_bar(NB * 2);

    // P2: per-block chunk scan (chunk <= 256)
    const int chunk = (N + NB - 1) / NB;
    const int i = b * chunk + tid;
    int v = (tid < chunk && i < N) ? __ldcg(&g_deg[i]) : 0;
    sh[tid] = v;
    __syncthreads();
    for (int off = 1; off < 256; off <<= 1) {
        int tv = (tid >= off) ? sh[tid - off] : 0;
        __syncthreads();
        sh[tid] += tv;
        __syncthreads();
    }
    int local_excl = sh[tid] - v;
    if (tid == 255) __stcg(&g_part[b], sh[255]);
    grid_bar(NB * 3);

    // P3: block 0 scans block totals
    if (b == 0) {
        int v2 = (tid < NB) ? __ldcg(&g_part[tid]) : 0;
        sh[tid] = v2;
        __syncthreads();
        for (int off = 1; off < 256; off <<= 1) {
            int tv = (tid >= off) ? sh[tid - off] : 0;
            __syncthreads();
            sh[tid] += tv;
            __syncthreads();
        }
        if (tid < NB) __stcg(&g_poff[tid], sh[tid] - v2);
        if (tid == 0) __stcg(&g_off[N], E);
    }
    grid_bar(NB * 4);

    // P4: finalize offsets
    {
        int po = __ldcg(&g_poff[b]);
        if (tid < chunk && i < N) {
            int vv = local_excl + po;
            __stcg(&g_off[i], vv);
            __stcg(&g_fill[i], vv);
        }
    }
    grid_bar(NB * 5);

    // P5: scatter edges into CSR (src pre-multiplied by H)
    for (int e = gid; e < E; e += gsz) {
        int d = __ldg(&dst[e]);
        int p = atomicAdd(&g_fill[d], 1);
        __stcg(&g_csr[p], (__ldg(&src[e]) * H) | (__ldg(&bond[e]) << 27));
    }

    // reset barrier state for next graph replay
    __syncthreads();
    if (tid == 0) {
        if (atomicAdd(&g_done, 1u) == NB - 1) {
            atomicExch(&g_bar, 0u);
            atomicExch(&g_done, 0u);
        }
    }
}

// ---------------- edge loop: dual-node, edge-major staging, smem ev table ----------------
__device__ __forceinline__ float dot_edge(const float* buf, const ull* w2d, float b2) {
    ull acc = 0ull;
#pragma unroll
    for (int j = 0; j < 8; j++) {
        ulonglong2 v = *(const ulonglong2*)&buf[4 * j];
        acc = fma2(v.x, w2d[2 * j], acc);
        acc = fma2(v.y, w2d[2 * j + 1], acc);
    }
    float lo, hi; unpackf2(acc, lo, hi);
    return lo + hi + b2;
}

__global__ void __launch_bounds__(128, 6) k_agg(
    const float* __restrict__ pre_w1,
    const float* __restrict__ pre_w2, const float* __restrict__ pre_b2, int N) {
    const int l = threadIdx.x & 31;
    const int t = threadIdx.x >> 5;
    __shared__ __align__(16) float rs[4][2][4][32];   // [warp][parity][edge-slot][feature]
    __shared__ float evtab[4][5][32];                 // [warp][bond][lane]

    ull w2d[16];
#pragma unroll
    for (int j = 0; j < 16; j++)
        w2d[j] = packf2(pre_w2[(t * FIN + 2 * j) * FIN + l],
                        pre_w2[(t * FIN + 2 * j + 1) * FIN + l]);
    const float b2 = pre_b2[t * FIN + l];

    {
        float w1c[FIN];
#pragma unroll
        for (int f = 0; f < FIN; f++) w1c[f] = pre_w1[(t * 96 + 64 + f) * FIN + l];
#pragma unroll
        for (int b = 0; b < 5; b++) {
            float et = g_enc[b * FIN + l];
            float a = 0.f;
#pragma unroll
            for (int f = 0; f < FIN; f++) a += __shfl_sync(FULLM, et, f) * w1c[f];
            evtab[t][b][l] = a;
        }
        __syncwarp();
    }
    const float* evs = &evtab[t][0][0];   // lane l reads evs[b*32+l]: bank-conflict-free
    const int off = t * FIN + l;
    const int half = (N + 1) >> 1;

    for (int n = blockIdx.x; n < half; n += gridDim.x) {
        const int nA = n, nB = n + half;
        const bool hasB = nB < N;
        float a0A = g_a0[nA * H + off];
        int e0A = g_off[nA], e1A = g_off[nA + 1];
        float a0B = 0.f; int e0B = 0, e1B = 0;
        if (hasB) { a0B = g_a0[nB * H + off]; e0B = g_off[nB]; e1B = g_off[nB + 1]; }
        const int cntA = e1A - e0A, cntB = e1B - e0B;
        const int pAcnt = cntA >> 1, pBcnt = cntB >> 1;
        const int np = max(pAcnt, pBcnt);

        float sA = 0.f, qA = 0.f, sB = 0.f, qB = 0.f;
        float minA = FLT_MAX, maxA = -FLT_MAX, minB = FLT_MAX, maxB = -FLT_MAX;

        float paA = 0.f, pbA = 0.f, paB = 0.f, pbB = 0.f;
        float evaA = 0.f, evbA = 0.f, evaB = 0.f, evbB = 0.f;
        if (pAcnt > 0) {
            int k0 = g_csr[e0A], k1 = g_csr[e0A + 1];
            evaA = evs[(k0 >> 27) * 32 + l];
            evbA = evs[(k1 >> 27) * 32 + l];
            paA = g_p[(k0 & 0x07ffffff) + off];
            pbA = g_p[(k1 & 0x07ffffff) + off];
        }
        if (pBcnt > 0) {
            int k0 = g_csr[e0B], k1 = g_csr[e0B + 1];
            evaB = evs[(k0 >> 27) * 32 + l];
            evbB = evs[(k1 >> 27) * 32 + l];
            paB = g_p[(k0 & 0x07ffffff) + off];
            pbB = g_p[(k1 & 0x07ffffff) + off];
        }

        for (int i = 0; i < np; i++) {
            const int par = i & 1;
            const bool dA = i < pAcnt, dB = i < pBcnt;
            if (dA) {
                rs[t][par][0][l] = fmaxf(a0A + evaA + paA, 0.f);
                rs[t][par][1][l] = fmaxf(a0A + evbA + pbA, 0.f);
            }
            if (dB) {
                rs[t][par][2][l] = fmaxf(a0B + evaB + paB, 0.f);
                rs[t][par][3][l] = fmaxf(a0B + evbB + pbB, 0.f);
            }
            if (i + 1 < pAcnt) {
                int idx = e0A + 2 * (i + 1);
                int k0 = g_csr[idx], k1 = g_csr[idx + 1];
                evaA = evs[(k0 >> 27) * 32 + l];
                evbA = evs[(k1 >> 27) * 32 + l];
                paA = g_p[(k0 & 0x07ffffff) + off];
                pbA = g_p[(k1 & 0x07ffffff) + off];
            }
            if (i + 1 < pBcnt) {
                int idx = e0B + 2 * (i + 1);
                int k0 = g_csr[idx], k1 = g_csr[idx + 1];
                evaB = evs[(k0 >> 27) * 32 + l];
                evbB = evs[(k1 >> 27) * 32 + l];
                paB = g_p[(k0 & 0x07ffffff) + off];
                pbB = g_p[(k1 & 0x07ffffff) + off];
            }
            __syncwarp();
            if (dA) {
                float m0 = dot_edge(rs[t][par][0], w2d, b2);
                float m1 = dot_edge(rs[t][par][1], w2d, b2);
                sA += m0 + m1;
                qA = fmaf(m0, m0, qA); qA = fmaf(m1, m1, qA);
                minA = fminf(minA, fminf(m0, m1));
                maxA = fmaxf(maxA, fmaxf(m0, m1));
            }
            if (dB) {
                float m0 = dot_edge(rs[t][par][2], w2d, b2);
                float m1 = dot_edge(rs[t][par][3], w2d, b2);
                sB += m0 + m1;
                qB = fmaf(m0, m0, qB); qB = fmaf(m1, m1, qB);
                minB = fminf(minB, fminf(m0, m1));
                maxB = fmaxf(maxB, fmaxf(m0, m1));
            }
        }

        const bool tA = (cntA & 1) != 0, tB = (cntB & 1) != 0;
        if (tA | tB) {
            const int par = np & 1;
            if (tA) {
                int k = g_csr[e1A - 1];
                float p = g_p[(k & 0x07ffffff) + off];
                rs[t][par][0][l] = fmaxf(a0A + evs[(k >> 27) * 32 + l] + p, 0.f);
            }
            if (tB) {
                int k = g_csr[e1B - 1];
                float p = g_p[(k & 0x07ffffff) + off];
                rs[t][par][2][l] = fmaxf(a0B + evs[(k >> 27) * 32 + l] + p, 0.f);
            }
            __syncwarp();
            if (tA) {
                float m0 = dot_edge(rs[t][par][0], w2d, b2);
                sA += m0; qA = fmaf(m0, m0, qA);
                minA = fminf(minA, m0); maxA = fmaxf(maxA, m0);
            }
            if (tB) {
                float m0 = dot_edge(rs[t][par][2], w2d, b2);
                sB += m0; qB = fmaf(m0, m0, qB);
                minB = fminf(minB, m0); maxB = fmaxf(maxB, m0);
            }
        }

        {
            float c1 = fmaxf((float)cntA, 1.f);
            float mean = sA / c1;
            float stdv = sqrtf(fmaxf(qA / c1 - mean * mean, 0.f) + 1e-5f);
            float mn = minA, mx = maxA;
            if (cntA == 0) { mn = 0.f; mx = 0.f; }
            float* o = g_agg + (size_t)(nA * T + t) * 5 * FIN + l;
            o[0 * FIN] = sA; o[1 * FIN] = mean; o[2 * FIN] = mn;
            o[3 * FIN] = mx; o[4 * FIN] = stdv;
        }
        if (hasB) {
            float c1 = fmaxf((float)cntB, 1.f);
            float mean = sB / c1;
            float stdv = sqrtf(fmaxf(qB / c1 - mean * mean, 0.f) + 1e-5f);
            float mn = minB, mx = maxB;
            if (cntB == 0) { mn = 0.f; mx = 0.f; }
            float* o = g_agg + (size_t)(nB * T + t) * 5 * FIN + l;
            o[0 * FIN] = sB; o[1 * FIN] = mean; o[2 * FIN] = mn;
            o[3 * FIN] = mx; o[4 * FIN] = stdv;
        }
    }
}

// ---------------- post-MLP: K-split cooperative GEMM ----------------
__global__ void __launch_bounds__(128, 5) k_post(
    const float* __restrict__ atom_x,
    const float* __restrict__ post_w1, const float* __restrict__ post_b1,
    const float* __restrict__ post_w2, const float* __restrict__ post_b2,
    int N) {
    const int t = blockIdx.y;
    const int w = threadIdx.x >> 5;
    const int g = threadIdx.x & 31;
    __shared__ __align__(16) float st[16][512];     // 32 KB
    __shared__ float red[4][16][32];                // 8 KB

    const float avg = g_avg_log;
    const float* w1 = post_w1 + (size_t)t * 512 * FIN;
    const int n0 = blockIdx.x * 16;

    // stage: warp w stages nodes 4w..4w+3
#pragma unroll
    for (int j2 = 0; j2 < 4; j2++) {
        const int j = w * 4 + j2;
        const int n = min(n0 + j, N - 1);
        int cnt = g_deg[n];
        float c1 = fmaxf((float)cnt, 1.f);
        float logd = logf(c1 + 1.f);
        float s1 = logd / avg, s2 = avg / logd;
        st[j][g] = atom_x[n * H + t * FIN + g];
        const float* ag = g_agg + (size_t)(n * T + t) * 5 * FIN;
#pragma unroll
        for (int a = 0; a < 5; a++) {
            float v = ag[a * FIN + g];
            st[j][32 + a * FIN + g] = v;
            st[j][192 + a * FIN + g] = v * s1;
            st[j][352 + a * FIN + g] = v * s2;
        }
    }
    __syncthreads();

    // compute: warp w covers K in [w*128, w*128+128)
    const float* wbase = w1 + (size_t)(w * 128) * FIN + g;
    const int fbase = w * 128;
    ull acc[16];
#pragma unroll
    for (int nd = 0; nd < 16; nd++) acc[nd] = 0ull;

#pragma unroll 4
    for (int fq = 0; fq < 32; fq++) {
        const int f = fbase + 4 * fq;
        float wv0 = wbase[(4 * fq + 0) * FIN];
        float wv1 = wbase[(4 * fq + 1) * FIN];
        float wv2 = wbase[(4 * fq + 2) * FIN];
        float wv3 = wbase[(4 * fq + 3) * FIN];
        ull wd0 = packf2(wv0, wv1);
        ull wd1 = packf2(wv2, wv3);
#pragma unroll
        for (int nd = 0; nd < 16; nd++) {
            ulonglong2 v = *(const ulonglong2*)&st[nd][f];
            acc[nd] = fma2(v.x, wd0, acc[nd]);
            acc[nd] = fma2(v.y, wd1, acc[nd]);
        }
    }
#pragma unroll
    for (int nd = 0; nd < 16; nd++) {
        float lo, hi; unpackf2(acc[nd], lo, hi);
        red[w][nd][g] = lo + hi;
    }
    __syncthreads();

    // epilogue: warp w finishes nodes 4w..4w+3
    const float b1 = post_b1[t * FIN + g];
    const float b2v = post_b2[t * FIN + g];
    float m0, m1, m2, m3;
    {
        const int j = w * 4;
        m0 = fmaxf(red[0][j+0][g] + red[1][j+0][g] + red[2][j+0][g] + red[3][j+0][g] + b1, 0.f);
        m1 = fmaxf(red[0][j+1][g] + red[1][j+1][g] + red[2][j+1][g] + red[3][j+1][g] + b1, 0.f);
        m2 = fmaxf(red[0][j+2][g] + red[1][j+2][g] + red[2][j+2][g] + red[3][j+2][g] + b1, 0.f);
        m3 = fmaxf(red[0][j+3][g] + red[1][j+3][g] + red[2][j+3][g] + red[3][j+3][g] + b1, 0.f);
    }
    float o0 = b2v, o1 = b2v, o2 = b2v, o3 = b2v;
#pragma unroll
    for (int f = 0; f < FIN; f++) {
        float wv = __ldg(&post_w2[(t * FIN + f) * FIN + g]);
        o0 += __shfl_sync(FULLM, m0, f) * wv;
        o1 += __shfl_sync(FULLM, m1, f) * wv;
        o2 += __shfl_sync(FULLM, m2, f) * wv;
        o3 += __shfl_sync(FULLM, m3, f) * wv;
    }
    float oo[4] = {o0, o1, o2, o3};
#pragma unroll
    for (int j2 = 0; j2 < 4; j2++) {
        int n = n0 + w * 4 + j2;
        if (n < N) g_y[n * H + t * FIN + g] = oo[j2];
    }
}

// ---------------- final linear + LayerNorm + ReLU residual (8-node f32x2) ----------------
// Nodes j and j+4 packed into one f32x2 accumulator lane; 8 nodes per group.
__global__ void __launch_bounds__(128) k_final(
    const float* __restrict__ atom_x,
    const float* __restrict__ lin_w, const float* __restrict__ lin_b,
    const float* __restrict__ ln_g, const float* __restrict__ ln_b,
    float* __restrict__ out, int N) {
    const int o = threadIdx.x;
    const int wid = o >> 5, l = o & 31;
    __shared__ __align__(16) float2 sy2[4][H];   // pair p: (node p, node p+4)
    __shared__ float red_s[8][4], red_q[8][4];
    const float lb = lin_b[o], gamma = ln_g[o], beta = ln_b[o];

    for (int grp = 0; grp < 2; grp++) {
        int n0 = blockIdx.x * 16 + grp * 8;
        __syncthreads();
        // stage: node j -> pair (j&3), half (j>>2)
#pragma unroll
        for (int j = 0; j < 8; j++) {
            int n = min(n0 + j, N - 1);
            ((float*)&sy2[j & 3][0])[2 * o + (j >> 2)] = g_y[n * H + o];
        }
        __syncthreads();
        ull a0 = packf2(lb, lb), a1 = a0, a2 = a0, a3 = a0;
#pragma unroll 4
        for (int kk = 0; kk < 64; kk++) {
            int k = 2 * kk;
            ulonglong2 v0 = *(const ulonglong2*)&sy2[0][k];
            ulonglong2 v1 = *(const ulonglong2*)&sy2[1][k];
            ulonglong2 v2 = *(const ulonglong2*)&sy2[2][k];
            ulonglong2 v3 = *(const ulonglong2*)&sy2[3][k];
            float wv0 = lin_w[k * H + o];
            float wv1 = lin_w[(k + 1) * H + o];
            ull wd0 = packf2(wv0, wv0), wd1 = packf2(wv1, wv1);
            a0 = fma2(v0.x, wd0, a0); a0 = fma2(v0.y, wd1, a0);
            a1 = fma2(v1.x, wd0, a1); a1 = fma2(v1.y, wd1, a1);
            a2 = fma2(v2.x, wd0, a2); a2 = fma2(v2.y, wd1, a2);
            a3 = fma2(v3.x, wd0, a3); a3 = fma2(v3.y, wd1, a3);
        }
        float acc[8];
        unpackf2(a0, acc[0], acc[4]);
        unpackf2(a1, acc[1], acc[5]);
        unpackf2(a2, acc[2], acc[6]);
        unpackf2(a3, acc[3], acc[7]);
#pragma unroll
        for (int j = 0; j < 8; j++) {
            float s = acc[j], q = acc[j] * acc[j];
#pragma unroll
            for (int off = 16; off > 0; off >>= 1) {
                s += __shfl_xor_sync(FULLM, s, off);
                q += __shfl_xor_sync(FULLM, q, off);
            }
            if (l == 0) { red_s[j][wid] = s; red_q[j][wid] = q; }
        }
        __syncthreads();
#pragma unroll
        for (int j = 0; j < 8; j++) {
            int n = n0 + j;
            if (n >= N) continue;
            float s = red_s[j][0] + red_s[j][1] + red_s[j][2] + red_s[j][3];
            float q = red_q[j][0] + red_q[j][1] + red_q[j][2] + red_q[j][3];
            float mu = s * (1.f / 128.f);
            float var = q * (1.f / 128.f) - mu * mu;
            float v = (acc[j] - mu) * rsqrtf(var + 1e-5f) * gamma + beta;
            out[n * H + o] = atom_x[n * H + o] + fmaxf(v, 0.f);
        }
    }
}

// ---------------- launch ----------------
extern "C" void kernel_launch(void* const* d_in, const int* in_sizes, int n_in,
                              void* d_out, int out_size) {
    const float* atom_x  = (const float*)d_in[0];
    const int*   bond_x  = (const int*)d_in[1];
    const int*   edge_ix = (const int*)d_in[2];
    const int*   mol_deg = (const int*)d_in[3];
    const float* bond_emb = (const float*)d_in[4];
    const float* enc_w   = (const float*)d_in[5];
    const float* enc_b   = (const float*)d_in[6];
    const float* pre_w1  = (const float*)d_in[7];
    const float* pre_b1  = (const float*)d_in[8];
    const float* pre_w2  = (const float*)d_in[9];
    const float* pre_b2  = (const float*)d_in[10];
    const float* post_w1 = (const float*)d_in[11];
    const float* post_b1 = (const float*)d_in[12];
    const float* post_w2 = (const float*)d_in[13];
    const float* post_b2 = (const float*)d_in[14];
    const float* lin_w   = (const float*)d_in[15];
    const float* lin_b   = (const float*)d_in[16];
    const float* ln_g    = (const float*)d_in[17];
    const float* ln_b    = (const float*)d_in[18];
    float* out = (float*)d_out;

    int N = in_sizes[0] / H;
    int E = in_sizes[1];
    const int* src = edge_ix;
    const int* dst = edge_ix + E;

    k_setup<<<NB, 256>>>(dst, src, bond_x, atom_x, pre_w1, pre_b1,
                         mol_deg, bond_emb, enc_w, enc_b, N, E);            // 0
    k_agg<<<888, 128>>>(pre_w1, pre_w2, pre_b2, N);                         // 1
    k_post<<<dim3((N + 15) / 16, T), 128>>>(atom_x, post_w1, post_b1, post_w2, post_b2, N);  // 2
    k_final<<<(N + 15) / 16, 128>>>(atom_x, lin_w, lin_b, ln_g, ln_b, out, N);               // 3 <- ncu
}

// round 10
// speedup vs baseline: 1.4054x; 1.0146x over previous
#include <cuda_runtime.h>
#include <math.h>
#include <float.h>

#define NMAX 20000
#define EMAX 320000
#define H 128
#define T 4
#define FIN 32
#define FULLM 0xffffffffu
#define NB 132   // resident blocks for fused setup

typedef unsigned long long ull;

// ---------------- f32x2 packed helpers ----------------
__device__ __forceinline__ ull packf2(float lo, float hi) {
    ull r;
    asm("mov.b64 %0, {%1, %2};" : "=l"(r) : "r"(__float_as_uint(lo)), "r"(__float_as_uint(hi)));
    return r;
}
__device__ __forceinline__ void unpackf2(ull v, float& lo, float& hi) {
    unsigned int a, b;
    asm("mov.b64 {%0, %1}, %2;" : "=r"(a), "=r"(b) : "l"(v));
    lo = __uint_as_float(a); hi = __uint_as_float(b);
}
__device__ __forceinline__ ull fma2(ull a, ull b, ull c) {
    ull d;
    asm("fma.rn.f32x2 %0, %1, %2, %3;" : "=l"(d) : "l"(a), "l"(b), "l"(c));
    return d;
}
__device__ __forceinline__ ull add2(ull a, ull b) {
    ull d;
    asm("add.rn.f32x2 %0, %1, %2;" : "=l"(d) : "l"(a), "l"(b));
    return d;
}

// ---------------- device scratch ----------------
__device__ float g_avg_log;
__device__ float g_enc[5 * FIN];
__device__ int   g_deg[NMAX];
__device__ int   g_off[NMAX + 1];
__device__ int   g_fill[NMAX];
__device__ int   g_csr[EMAX];                 // packed: (src*H) | (bond<<27)
__device__ int   g_part[NB];
__device__ int   g_poff[NB];
__device__ float g_a0[(size_t)NMAX * H];
__device__ float g_p [(size_t)NMAX * H];
__device__ float g_agg[(size_t)NMAX * T * 5 * FIN];
__device__ unsigned int g_bar;
__device__ unsigned int g_done;

// ---------------- fused setup: zero + hist + PRE + SCALARS + scan + scatter ----------------
__device__ __forceinline__ void grid_bar(unsigned target) {
    __syncthreads();
    if (threadIdx.x == 0) {
        __threadfence();
        atomicAdd(&g_bar, 1u);
        while (*((volatile unsigned int*)&g_bar) < target) { }
        __threadfence();
    }
    __syncthreads();
}

__global__ void __launch_bounds__(256) k_setup(
    const int* __restrict__ dst, const int* __restrict__ src,
    const int* __restrict__ bond,
    const float* __restrict__ atom_x,
    const float* __restrict__ pre_w1, const float* __restrict__ pre_b1,
    const int* __restrict__ mol_deg,
    const float* __restrict__ bond_emb,
    const float* __restrict__ enc_w, const float* __restrict__ enc_b,
    int N, int E) {
    const int tid = threadIdx.x, b = blockIdx.x;
    const int gsz = NB * 256;
    const int gid = b * 256 + tid;
    __shared__ int sh[256];
    __shared__ float sf[256], sf2[256];

    // P0: zero degree counters
    for (int i = gid; i < N; i += gsz) __stcg(&g_deg[i], 0);
    grid_bar(NB * 1);

    // P1: degree histogram
    for (int e = gid; e < E; e += gsz) atomicAdd(&g_deg[__ldg(&dst[e])], 1);

    // SCALARS (block 1, independent of hist): avg_log + bond-encode table
    if (b == 1) {
        float num = 0.f, den = 0.f;
        if (tid < 128) {
            float d = (float)mol_deg[tid];
            num = logf((float)tid + 1.0f) * d;
            den = d;
        }
        sf[tid] = num; sf2[tid] = den;
        __syncthreads();
        for (int off = 128; off > 0; off >>= 1) {
            if (tid < off) { sf[tid] += sf[tid + off]; sf2[tid] += sf2[tid + off]; }
            __syncthreads();
        }
        if (tid == 0) g_avg_log = sf[0] / sf2[0];
        if (tid < 5 * FIN) {
            int bb = tid >> 5, g = tid & 31;
            float a = enc_b[g];
            for (int k = 0; k < H; k++) a += bond_emb[bb * H + k] * enc_w[k * FIN + g];
            g_enc[bb * FIN + g] = a;
        }
        __syncthreads();
    }

    // PRE (independent of hist): A0 = b1 + W1a.x, P = W1b.x
    {
        const int l = tid & 31;
        const int w = tid >> 5;
        const int t = w & 3;
        float w1a[FIN], w1b[FIN];
#pragma unroll
        for (int f = 0; f < FIN; f++) w1a[f] = pre_w1[(t * 96 + f) * FIN + l];
#pragma unroll
        for (int f = 0; f < FIN; f++) w1b[f] = pre_w1[(t * 96 + 32 + f) * FIN + l];
        const float b1 = pre_b1[t * FIN + l];
        for (int n = b * 2 + (w >> 2); n < N; n += NB * 2) {
            float x = atom_x[n * H + t * FIN + l];
            float a0 = b1, p = 0.f;
#pragma unroll
            for (int f = 0; f < FIN; f++) {
                float xf = __shfl_sync(FULLM, x, f);
                a0 += xf * w1a[f];
                p  += xf * w1b[f];
            }
            g_a0[n * H + t * FIN + l] = a0;
            g_p [n * H + t * FIN + l] = p;
        }
    }
    grid_bar(NB * 2);

    // P2: per-block chunk scan (chunk <= 256)
    const int chunk = (N + NB - 1) / NB;
    const int i = b * chunk + tid;
    int v = (tid < chunk && i < N) ? __ldcg(&g_deg[i]) : 0;
    sh[tid] = v;
    __syncthreads();
    for (int off = 1; off < 256; off <<= 1) {
        int tv = (tid >= off) ? sh[tid - off] : 0;
        __syncthreads();
        sh[tid] += tv;
        __syncthreads();
    }
    int local_excl = sh[tid] - v;
    if (tid == 255) __stcg(&g_part[b], sh[255]);
    grid_bar(NB * 3);

    // P3: block 0 scans block totals
    if (b == 0) {
        int v2 = (tid < NB) ? __ldcg(&g_part[tid]) : 0;
        sh[tid] = v2;
        __syncthreads();
        for (int off = 1; off < 256; off <<= 1) {
            int tv = (tid >= off) ? sh[tid - off] : 0;
            __syncthreads();
            sh[tid] += tv;
            __syncthreads();
        }
        if (tid < NB) __stcg(&g_poff[tid], sh[tid] - v2);
        if (tid == 0) __stcg(&g_off[N], E);
    }
    grid_bar(NB * 4);

    // P4: finalize offsets
    {
        int po = __ldcg(&g_poff[b]);
        if (tid < chunk && i < N) {
            int vv = local_excl + po;
            __stcg(&g_off[i], vv);
            __stcg(&g_fill[i], vv);
        }
    }
    grid_bar(NB * 5);

    // P5: scatter edges into CSR (src pre-multiplied by H)
    for (int e = gid; e < E; e += gsz) {
        int d = __ldg(&dst[e]);
        int p = atomicAdd(&g_fill[d], 1);
        __stcg(&g_csr[p], (__ldg(&src[e]) * H) | (__ldg(&bond[e]) << 27));
    }

    // reset barrier state for next graph replay
    __syncthreads();
    if (tid == 0) {
        if (atomicAdd(&g_done, 1u) == NB - 1) {
            atomicExch(&g_bar, 0u);
            atomicExch(&g_done, 0u);
        }
    }
}

// ---------------- edge loop: dual-node, edge-major staging, smem ev table ----------------
__device__ __forceinline__ float dot_edge(const float* buf, const ull* w2d, float b2) {
    ull acc = 0ull;
#pragma unroll
    for (int j = 0; j < 8; j++) {
        ulonglong2 v = *(const ulonglong2*)&buf[4 * j];
        acc = fma2(v.x, w2d[2 * j], acc);
        acc = fma2(v.y, w2d[2 * j + 1], acc);
    }
    float lo, hi; unpackf2(acc, lo, hi);
    return lo + hi + b2;
}

__global__ void __launch_bounds__(128, 6) k_agg(
    const float* __restrict__ pre_w1,
    const float* __restrict__ pre_w2, const float* __restrict__ pre_b2, int N) {
    const int l = threadIdx.x & 31;
    const int t = threadIdx.x >> 5;
    __shared__ __align__(16) float rs[4][2][4][32];   // [warp][parity][edge-slot][feature]
    __shared__ float evtab[4][5][32];                 // [warp][bond][lane]

    ull w2d[16];
#pragma unroll
    for (int j = 0; j < 16; j++)
        w2d[j] = packf2(pre_w2[(t * FIN + 2 * j) * FIN + l],
                        pre_w2[(t * FIN + 2 * j + 1) * FIN + l]);
    const float b2 = pre_b2[t * FIN + l];

    {
        float w1c[FIN];
#pragma unroll
        for (int f = 0; f < FIN; f++) w1c[f] = pre_w1[(t * 96 + 64 + f) * FIN + l];
#pragma unroll
        for (int b = 0; b < 5; b++) {
            float et = g_enc[b * FIN + l];
            float a = 0.f;
#pragma unroll
            for (int f = 0; f < FIN; f++) a += __shfl_sync(FULLM, et, f) * w1c[f];
            evtab[t][b][l] = a;
        }
        __syncwarp();
    }
    const float* evs = &evtab[t][0][0];   // lane l reads evs[b*32+l]: bank-conflict-free
    const int off = t * FIN + l;
    const int half = (N + 1) >> 1;

    for (int n = blockIdx.x; n < half; n += gridDim.x) {
        const int nA = n, nB = n + half;
        const bool hasB = nB < N;
        float a0A = g_a0[nA * H + off];
        int e0A = g_off[nA], e1A = g_off[nA + 1];
        float a0B = 0.f; int e0B = 0, e1B = 0;
        if (hasB) { a0B = g_a0[nB * H + off]; e0B = g_off[nB]; e1B = g_off[nB + 1]; }
        const int cntA = e1A - e0A, cntB = e1B - e0B;
        const int pAcnt = cntA >> 1, pBcnt = cntB >> 1;
        const int np = max(pAcnt, pBcnt);

        float sA = 0.f, qA = 0.f, sB = 0.f, qB = 0.f;
        float minA = FLT_MAX, maxA = -FLT_MAX, minB = FLT_MAX, maxB = -FLT_MAX;

        float paA = 0.f, pbA = 0.f, paB = 0.f, pbB = 0.f;
        float evaA = 0.f, evbA = 0.f, evaB = 0.f, evbB = 0.f;
        if (pAcnt > 0) {
            int k0 = g_csr[e0A], k1 = g_csr[e0A + 1];
            evaA = evs[(k0 >> 27) * 32 + l];
            evbA = evs[(k1 >> 27) * 32 + l];
            paA = g_p[(k0 & 0x07ffffff) + off];
            pbA = g_p[(k1 & 0x07ffffff) + off];
        }
        if (pBcnt > 0) {
            int k0 = g_csr[e0B], k1 = g_csr[e0B + 1];
            evaB = evs[(k0 >> 27) * 32 + l];
            evbB = evs[(k1 >> 27) * 32 + l];
            paB = g_p[(k0 & 0x07ffffff) + off];
            pbB = g_p[(k1 & 0x07ffffff) + off];
        }

        for (int i = 0; i < np; i++) {
            const int par = i & 1;
            const bool dA = i < pAcnt, dB = i < pBcnt;
            if (dA) {
                rs[t][par][0][l] = fmaxf(a0A + evaA + paA, 0.f);
                rs[t][par][1][l] = fmaxf(a0A + evbA + pbA, 0.f);
            }
            if (dB) {
                rs[t][par][2][l] = fmaxf(a0B + evaB + paB, 0.f);
                rs[t][par][3][l] = fmaxf(a0B + evbB + pbB, 0.f);
            }
            if (i + 1 < pAcnt) {
                int idx = e0A + 2 * (i + 1);
                int k0 = g_csr[idx], k1 = g_csr[idx + 1];
                evaA = evs[(k0 >> 27) * 32 + l];
                evbA = evs[(k1 >> 27) * 32 + l];
                paA = g_p[(k0 & 0x07ffffff) + off];
                pbA = g_p[(k1 & 0x07ffffff) + off];
            }
            if (i + 1 < pBcnt) {
                int idx = e0B + 2 * (i + 1);
                int k0 = g_csr[idx], k1 = g_csr[idx + 1];
                evaB = evs[(k0 >> 27) * 32 + l];
                evbB = evs[(k1 >> 27) * 32 + l];
                paB = g_p[(k0 & 0x07ffffff) + off];
                pbB = g_p[(k1 & 0x07ffffff) + off];
            }
            __syncwarp();
            if (dA) {
                float m0 = dot_edge(rs[t][par][0], w2d, b2);
                float m1 = dot_edge(rs[t][par][1], w2d, b2);
                sA += m0 + m1;
                qA = fmaf(m0, m0, qA); qA = fmaf(m1, m1, qA);
                minA = fminf(minA, fminf(m0, m1));
                maxA = fmaxf(maxA, fmaxf(m0, m1));
            }
            if (dB) {
                float m0 = dot_edge(rs[t][par][2], w2d, b2);
                float m1 = dot_edge(rs[t][par][3], w2d, b2);
                sB += m0 + m1;
                qB = fmaf(m0, m0, qB); qB = fmaf(m1, m1, qB);
                minB = fminf(minB, fminf(m0, m1));
                maxB = fmaxf(maxB, fmaxf(m0, m1));
            }
        }

        const bool tA = (cntA & 1) != 0, tB = (cntB & 1) != 0;
        if (tA | tB) {
            const int par = np & 1;
            if (tA) {
                int k = g_csr[e1A - 1];
                float p = g_p[(k & 0x07ffffff) + off];
                rs[t][par][0][l] = fmaxf(a0A + evs[(k >> 27) * 32 + l] + p, 0.f);
            }
            if (tB) {
                int k = g_csr[e1B - 1];
                float p = g_p[(k & 0x07ffffff) + off];
                rs[t][par][2][l] = fmaxf(a0B + evs[(k >> 27) * 32 + l] + p, 0.f);
            }
            __syncwarp();
            if (tA) {
                float m0 = dot_edge(rs[t][par][0], w2d, b2);
                sA += m0; qA = fmaf(m0, m0, qA);
                minA = fminf(minA, m0); maxA = fmaxf(maxA, m0);
            }
            if (tB) {
                float m0 = dot_edge(rs[t][par][2], w2d, b2);
                sB += m0; qB = fmaf(m0, m0, qB);
                minB = fminf(minB, m0); maxB = fmaxf(maxB, m0);
            }
        }

        {
            float c1 = fmaxf((float)cntA, 1.f);
            float mean = sA / c1;
            float stdv = sqrtf(fmaxf(qA / c1 - mean * mean, 0.f) + 1e-5f);
            float mn = minA, mx = maxA;
            if (cntA == 0) { mn = 0.f; mx = 0.f; }
            float* o = g_agg + (size_t)(nA * T + t) * 5 * FIN + l;
            o[0 * FIN] = sA; o[1 * FIN] = mean; o[2 * FIN] = mn;
            o[3 * FIN] = mx; o[4 * FIN] = stdv;
        }
        if (hasB) {
            float c1 = fmaxf((float)cntB, 1.f);
            float mean = sB / c1;
            float stdv = sqrtf(fmaxf(qB / c1 - mean * mean, 0.f) + 1e-5f);
            float mn = minB, mx = maxB;
            if (cntB == 0) { mn = 0.f; mx = 0.f; }
            float* o = g_agg + (size_t)(nB * T + t) * 5 * FIN + l;
            o[0 * FIN] = sB; o[1 * FIN] = mean; o[2 * FIN] = mn;
            o[3 * FIN] = mx; o[4 * FIN] = stdv;
        }
    }
}

// ---------------- fused tail: post-MLP (all 4 towers) + final linear + LayerNorm ----------------
// Block = 16 nodes. Loops towers; warp w owns nodes 4w..4w+3; per-tower K-split GEMM
// (warp w covers K rows [w*128,(w+1)*128) of the tower), epilogue produces y values in
// registers which immediately accumulate the final-linear partials (f32x2 packed).
__global__ void __launch_bounds__(128, 4) k_tail(
    const float* __restrict__ atom_x,
    const float* __restrict__ post_w1, const float* __restrict__ post_b1,
    const float* __restrict__ post_w2, const float* __restrict__ post_b2,
    const float* __restrict__ lin_w, const float* __restrict__ lin_b,
    const float* __restrict__ ln_g, const float* __restrict__ ln_b,
    float* __restrict__ out, int N) {
    const int w = threadIdx.x >> 5;
    const int g = threadIdx.x & 31;
    __shared__ __align__(16) float st[16][512];     // 32 KB, re-staged per tower
    __shared__ float red[4][16][32];                // 8 KB
    __shared__ float s1s[16], s2s[16];

    const int n0 = blockIdx.x * 16;

    if (threadIdx.x < 16) {
        int n = min(n0 + threadIdx.x, N - 1);
        float avg = g_avg_log;
        float c1 = fmaxf((float)g_deg[n], 1.f);
        float logd = logf(c1 + 1.f);
        s1s[threadIdx.x] = logd / avg;
        s2s[threadIdx.x] = avg / logd;
    }
    // final-linear accumulators: [node j2][oc-pair]; pair 0 = (o=g, o=32+g), pair 1 = (o=64+g, o=96+g)
    ull facc[4][2];
#pragma unroll
    for (int j2 = 0; j2 < 4; j2++) { facc[j2][0] = 0ull; facc[j2][1] = 0ull; }
    __syncthreads();

    for (int t = 0; t < T; t++) {
        // stage tower t features for this warp's 4 nodes
#pragma unroll
        for (int j2 = 0; j2 < 4; j2++) {
            const int j = w * 4 + j2;
            const int n = min(n0 + j, N - 1);
            float s1 = s1s[j], s2 = s2s[j];
            st[j][g] = atom_x[n * H + t * FIN + g];
            const float* ag = g_agg + (size_t)(n * T + t) * 5 * FIN;
#pragma unroll
            for (int a = 0; a < 5; a++) {
                float v = ag[a * FIN + g];
                st[j][32 + a * FIN + g] = v;
                st[j][192 + a * FIN + g] = v * s1;
                st[j][352 + a * FIN + g] = v * s2;
            }
        }
        __syncthreads();

        // K-split GEMM: warp w covers K in [w*128, w*128+128)
        const float* wbase = post_w1 + (size_t)t * 512 * FIN + (size_t)(w * 128) * FIN + g;
        const int fbase = w * 128;
        ull acc[16];
#pragma unroll
        for (int nd = 0; nd < 16; nd++) acc[nd] = 0ull;
#pragma unroll 4
        for (int fq = 0; fq < 32; fq++) {
            const int f = fbase + 4 * fq;
            float wv0 = wbase[(4 * fq + 0) * FIN];
            float wv1 = wbase[(4 * fq + 1) * FIN];
            float wv2 = wbase[(4 * fq + 2) * FIN];
            float wv3 = wbase[(4 * fq + 3) * FIN];
            ull wd0 = packf2(wv0, wv1);
            ull wd1 = packf2(wv2, wv3);
#pragma unroll
            for (int nd = 0; nd < 16; nd++) {
                ulonglong2 v = *(const ulonglong2*)&st[nd][f];
                acc[nd] = fma2(v.x, wd0, acc[nd]);
                acc[nd] = fma2(v.y, wd1, acc[nd]);
            }
        }
#pragma unroll
        for (int nd = 0; nd < 16; nd++) {
            float lo, hi; unpackf2(acc[nd], lo, hi);
            red[w][nd][g] = lo + hi;
        }
        __syncthreads();

        // epilogue for this tower: warp w's 4 nodes
        const float b1 = post_b1[t * FIN + g];
        const float b2v = post_b2[t * FIN + g];
        const int j = w * 4;
        float m0 = fmaxf(red[0][j+0][g] + red[1][j+0][g] + red[2][j+0][g] + red[3][j+0][g] + b1, 0.f);
        float m1 = fmaxf(red[0][j+1][g] + red[1][j+1][g] + red[2][j+1][g] + red[3][j+1][g] + b1, 0.f);
        float m2 = fmaxf(red[0][j+2][g] + red[1][j+2][g] + red[2][j+2][g] + red[3][j+2][g] + b1, 0.f);
        float m3 = fmaxf(red[0][j+3][g] + red[1][j+3][g] + red[2][j+3][g] + red[3][j+3][g] + b1, 0.f);
        float o0 = b2v, o1 = b2v, o2 = b2v, o3 = b2v;
#pragma unroll
        for (int f = 0; f < FIN; f++) {
            float wv = __ldg(&post_w2[(t * FIN + f) * FIN + g]);
            o0 += __shfl_sync(FULLM, m0, f) * wv;
            o1 += __shfl_sync(FULLM, m1, f) * wv;
            o2 += __shfl_sync(FULLM, m2, f) * wv;
            o3 += __shfl_sync(FULLM, m3, f) * wv;
        }
        // accumulate final-linear partials: y[node][t*32+f] = shfl(o_j, f)
#pragma unroll
        for (int f = 0; f < FIN; f++) {
            const float* lw = lin_w + (size_t)(t * FIN + f) * H + g;
            ull wda = packf2(__ldg(&lw[0]),  __ldg(&lw[32]));
            ull wdb = packf2(__ldg(&lw[64]), __ldg(&lw[96]));
            float y0 = __shfl_sync(FULLM, o0, f);
            float y1 = __shfl_sync(FULLM, o1, f);
            float y2 = __shfl_sync(FULLM, o2, f);
            float y3 = __shfl_sync(FULLM, o3, f);
            ull yd0 = packf2(y0, y0), yd1 = packf2(y1, y1);
            ull yd2 = packf2(y2, y2), yd3 = packf2(y3, y3);
            facc[0][0] = fma2(yd0, wda, facc[0][0]); facc[0][1] = fma2(yd0, wdb, facc[0][1]);
            facc[1][0] = fma2(yd1, wda, facc[1][0]); facc[1][1] = fma2(yd1, wdb, facc[1][1]);
            facc[2][0] = fma2(yd2, wda, facc[2][0]); facc[2][1] = fma2(yd2, wdb, facc[2][1]);
            facc[3][0] = fma2(yd3, wda, facc[3][0]); facc[3][1] = fma2(yd3, wdb, facc[3][1]);
        }
        __syncthreads();   // st re-staged next tower
    }

    // final: bias + LayerNorm + ReLU residual (warp w handles its 4 nodes)
    const float lb0 = lin_b[g],      lb1 = lin_b[32 + g];
    const float lb2 = lin_b[64 + g], lb3 = lin_b[96 + g];
    const float ga0 = ln_g[g],      ga1 = ln_g[32 + g];
    const float ga2 = ln_g[64 + g], ga3 = ln_g[96 + g];
    const float be0 = ln_b[g],      be1 = ln_b[32 + g];
    const float be2 = ln_b[64 + g], be3 = ln_b[96 + g];

#pragma unroll
    for (int j2 = 0; j2 < 4; j2++) {
        int n = n0 + w * 4 + j2;
        float a0, a1, a2, a3;
        unpackf2(facc[j2][0], a0, a1);
        unpackf2(facc[j2][1], a2, a3);
        a0 += lb0; a1 += lb1; a2 += lb2; a3 += lb3;
        float s = a0 + a1 + a2 + a3;
        float q = a0 * a0 + a1 * a1 + a2 * a2 + a3 * a3;
#pragma unroll
        for (int off = 16; off > 0; off >>= 1) {
            s += __shfl_xor_sync(FULLM, s, off);
            q += __shfl_xor_sync(FULLM, q, off);
        }
        if (n < N) {
            float mu = s * (1.f / 128.f);
            float var = q * (1.f / 128.f) - mu * mu;
            float rstd = rsqrtf(var + 1e-5f);
            const float* ax = atom_x + (size_t)n * H;
            float* op = out + (size_t)n * H;
            op[g]      = ax[g]      + fmaxf((a0 - mu) * rstd * ga0 + be0, 0.f);
            op[32 + g] = ax[32 + g] + fmaxf((a1 - mu) * rstd * ga1 + be1, 0.f);
            op[64 + g] = ax[64 + g] + fmaxf((a2 - mu) * rstd * ga2 + be2, 0.f);
            op[96 + g] = ax[96 + g] + fmaxf((a3 - mu) * rstd * ga3 + be3, 0.f);
        }
    }
}

// ---------------- launch ----------------
extern "C" void kernel_launch(void* const* d_in, const int* in_sizes, int n_in,
                              void* d_out, int out_size) {
    const float* atom_x  = (const float*)d_in[0];
    const int*   bond_x  = (const int*)d_in[1];
    const int*   edge_ix = (const int*)d_in[2];
    const int*   mol_deg = (const int*)d_in[3];
    const float* bond_emb = (const float*)d_in[4];
    const float* enc_w   = (const float*)d_in[5];
    const float* enc_b   = (const float*)d_in[6];
    const float* pre_w1  = (const float*)d_in[7];
    const float* pre_b1  = (const float*)d_in[8];
    const float* pre_w2  = (const float*)d_in[9];
    const float* pre_b2  = (const float*)d_in[10];
    const float* post_w1 = (const float*)d_in[11];
    const float* post_b1 = (const float*)d_in[12];
    const float* post_w2 = (const float*)d_in[13];
    const float* post_b2 = (const float*)d_in[14];
    const float* lin_w   = (const float*)d_in[15];
    const float* lin_b   = (const float*)d_in[16];
    const float* ln_g    = (const float*)d_in[17];
    const float* ln_b    = (const float*)d_in[18];
    float* out = (float*)d_out;

    int N = in_sizes[0] / H;
    int E = in_sizes[1];
    const int* src = edge_ix;
    const int* dst = edge_ix + E;

    k_setup<<<NB, 256>>>(dst, src, bond_x, atom_x, pre_w1, pre_b1,
                         mol_deg, bond_emb, enc_w, enc_b, N, E);            // 0
    k_agg<<<888, 128>>>(pre_w1, pre_w2, pre_b2, N);                         // 1
    k_tail<<<(N + 15) / 16, 128>>>(atom_x, post_w1, post_b1, post_w2, post_b2,
                                   lin_w, lin_b, ln_g, ln_b, out, N);       // 2
}

// round 11
// speedup vs baseline: 1.5554x; 1.1067x over previous
#include <cuda_runtime.h>
#include <math.h>
#include <float.h>

#define NMAX 20000
#define EMAX 320000
#define H 128
#define T 4
#define FIN 32
#define FULLM 0xffffffffu
#define NB 132     // resident blocks for fused setup
#define STH 512    // k_setup threads per block

typedef unsigned long long ull;

// ---------------- f32x2 packed helpers ----------------
__device__ __forceinline__ ull packf2(float lo, float hi) {
    ull r;
    asm("mov.b64 %0, {%1, %2};" : "=l"(r) : "r"(__float_as_uint(lo)), "r"(__float_as_uint(hi)));
    return r;
}
__device__ __forceinline__ void unpackf2(ull v, float& lo, float& hi) {
    unsigned int a, b;
    asm("mov.b64 {%0, %1}, %2;" : "=r"(a), "=r"(b) : "l"(v));
    lo = __uint_as_float(a); hi = __uint_as_float(b);
}
__device__ __forceinline__ ull fma2(ull a, ull b, ull c) {
    ull d;
    asm("fma.rn.f32x2 %0, %1, %2, %3;" : "=l"(d) : "l"(a), "l"(b), "l"(c));
    return d;
}
__device__ __forceinline__ ull add2(ull a, ull b) {
    ull d;
    asm("add.rn.f32x2 %0, %1, %2;" : "=l"(d) : "l"(a), "l"(b));
    return d;
}

// ---------------- device scratch ----------------
__device__ float g_avg_log;
__device__ float g_enc[5 * FIN];
__device__ int   g_deg[NMAX];
__device__ int   g_off[NMAX + 1];
__device__ int   g_fill[NMAX];
__device__ int   g_csr[EMAX];                 // packed: (src*H) | (bond<<27)
__device__ int   g_part[NB];
__device__ int   g_poff[NB];
__device__ float g_a0[(size_t)NMAX * H];
__device__ float g_p [(size_t)NMAX * H];
__device__ float g_agg[(size_t)NMAX * T * 5 * FIN];
__device__ unsigned int g_bar;
__device__ unsigned int g_done;

// ---------------- fused setup: zero + hist + PRE + SCALARS + scan + scatter ----------------
__device__ __forceinline__ void grid_bar(unsigned target) {
    __syncthreads();
    if (threadIdx.x == 0) {
        __threadfence();
        atomicAdd(&g_bar, 1u);
        while (*((volatile unsigned int*)&g_bar) < target) { }
        __threadfence();
    }
    __syncthreads();
}

__global__ void __launch_bounds__(STH) k_setup(
    const int* __restrict__ dst, const int* __restrict__ src,
    const int* __restrict__ bond,
    const float* __restrict__ atom_x,
    const float* __restrict__ pre_w1, const float* __restrict__ pre_b1,
    const int* __restrict__ mol_deg,
    const float* __restrict__ bond_emb,
    const float* __restrict__ enc_w, const float* __restrict__ enc_b,
    int N, int E) {
    const int tid = threadIdx.x, b = blockIdx.x;
    const int gsz = NB * STH;
    const int gid = b * STH + tid;
    __shared__ int sh[STH];
    __shared__ float sf[256], sf2[256];

    // P0: zero degree counters
    for (int i = gid; i < N; i += gsz) __stcg(&g_deg[i], 0);
    grid_bar(NB * 1);

    // P1: degree histogram
    for (int e = gid; e < E; e += gsz) atomicAdd(&g_deg[__ldg(&dst[e])], 1);

    // SCALARS (block 1, independent of hist): avg_log + bond-encode table
    if (b == 1 && tid < 256) {
        float num = 0.f, den = 0.f;
        if (tid < 128) {
            float d = (float)mol_deg[tid];
            num = logf((float)tid + 1.0f) * d;
            den = d;
        }
        sf[tid] = num; sf2[tid] = den;
        __syncwarp();
        // reduce across 256 threads using shared (participants only; no blockwide sync needed
        // because only tid<256 touch sf, and the final write is by tid 0 after a fence loop)
    }
    if (b == 1) {
        __syncthreads();
        if (tid < 128) { sf[tid] += sf[tid + 128]; sf2[tid] += sf2[tid + 128]; }
        __syncthreads();
        if (tid < 64) { sf[tid] += sf[tid + 64]; sf2[tid] += sf2[tid + 64]; }
        __syncthreads();
        if (tid < 32) {
            float s = sf[tid] + sf[tid + 32];
            float d = sf2[tid] + sf2[tid + 32];
#pragma unroll
            for (int off = 16; off > 0; off >>= 1) {
                s += __shfl_down_sync(FULLM, s, off);
                d += __shfl_down_sync(FULLM, d, off);
            }
            if (tid == 0) g_avg_log = s / d;
        }
        if (tid < 5 * FIN) {
            int bb = tid >> 5, g = tid & 31;
            float a = enc_b[g];
            for (int k = 0; k < H; k++) a += bond_emb[bb * H + k] * enc_w[k * FIN + g];
            g_enc[bb * FIN + g] = a;
        }
        __syncthreads();
    }

    // PRE (independent of hist): A0 = b1 + W1a.x, P = W1b.x
    // 16 warps: warp w -> tower (w&3), node-group (w>>2) of 4
    {
        const int l = tid & 31;
        const int w = tid >> 5;
        const int t = w & 3;
        float w1a[FIN], w1b[FIN];
#pragma unroll
        for (int f = 0; f < FIN; f++) w1a[f] = pre_w1[(t * 96 + f) * FIN + l];
#pragma unroll
        for (int f = 0; f < FIN; f++) w1b[f] = pre_w1[(t * 96 + 32 + f) * FIN + l];
        const float b1 = pre_b1[t * FIN + l];
        for (int n = b * 4 + (w >> 2); n < N; n += NB * 4) {
            float x = atom_x[n * H + t * FIN + l];
            float a0 = b1, p = 0.f;
#pragma unroll
            for (int f = 0; f < FIN; f++) {
                float xf = __shfl_sync(FULLM, x, f);
                a0 += xf * w1a[f];
                p  += xf * w1b[f];
            }
            g_a0[n * H + t * FIN + l] = a0;
            g_p [n * H + t * FIN + l] = p;
        }
    }
    grid_bar(NB * 2);

    // P2: per-block chunk scan (chunk = ceil(N/NB) <= STH)
    const int chunk = (N + NB - 1) / NB;
    const int i = b * chunk + tid;
    int v = (tid < chunk && i < N) ? __ldcg(&g_deg[i]) : 0;
    sh[tid] = v;
    __syncthreads();
    for (int off = 1; off < STH; off <<= 1) {
        int tv = (tid >= off) ? sh[tid - off] : 0;
        __syncthreads();
        sh[tid] += tv;
        __syncthreads();
    }
    int local_excl = sh[tid] - v;
    if (tid == STH - 1) __stcg(&g_part[b], sh[STH - 1]);
    grid_bar(NB * 3);

    // P3: block 0 scans block totals
    if (b == 0) {
        int v2 = (tid < NB) ? __ldcg(&g_part[tid]) : 0;
        sh[tid] = v2;
        __syncthreads();
        for (int off = 1; off < STH; off <<= 1) {
            int tv = (tid >= off) ? sh[tid - off] : 0;
            __syncthreads();
            sh[tid] += tv;
            __syncthreads();
        }
        if (tid < NB) __stcg(&g_poff[tid], sh[tid] - v2);
        if (tid == 0) __stcg(&g_off[N], E);
    }
    grid_bar(NB * 4);

    // P4: finalize offsets
    {
        int po = __ldcg(&g_poff[b]);
        if (tid < chunk && i < N) {
            int vv = local_excl + po;
            __stcg(&g_off[i], vv);
            __stcg(&g_fill[i], vv);
        }
    }
    grid_bar(NB * 5);

    // P5: scatter edges into CSR (src pre-multiplied by H)
    for (int e = gid; e < E; e += gsz) {
        int d = __ldg(&dst[e]);
        int p = atomicAdd(&g_fill[d], 1);
        __stcg(&g_csr[p], (__ldg(&src[e]) * H) | (__ldg(&bond[e]) << 27));
    }

    // reset barrier state for next graph replay
    __syncthreads();
    if (tid == 0) {
        if (atomicAdd(&g_done, 1u) == NB - 1) {
            atomicExch(&g_bar, 0u);
            atomicExch(&g_done, 0u);
        }
    }
}

// ---------------- edge loop: dual-node, edge-major staging, smem ev table ----------------
__device__ __forceinline__ float dot_edge(const float* buf, const ull* w2d, float b2) {
    ull acc = 0ull;
#pragma unroll
    for (int j = 0; j < 8; j++) {
        ulonglong2 v = *(const ulonglong2*)&buf[4 * j];
        acc = fma2(v.x, w2d[2 * j], acc);
        acc = fma2(v.y, w2d[2 * j + 1], acc);
    }
    float lo, hi; unpackf2(acc, lo, hi);
    return lo + hi + b2;
}

__global__ void __launch_bounds__(128, 6) k_agg(
    const float* __restrict__ pre_w1,
    const float* __restrict__ pre_w2, const float* __restrict__ pre_b2, int N) {
    const int l = threadIdx.x & 31;
    const int t = threadIdx.x >> 5;
    __shared__ __align__(16) float rs[4][2][4][32];   // [warp][parity][edge-slot][feature]
    __shared__ float evtab[4][5][32];                 // [warp][bond][lane]

    ull w2d[16];
#pragma unroll
    for (int j = 0; j < 16; j++)
        w2d[j] = packf2(pre_w2[(t * FIN + 2 * j) * FIN + l],
                        pre_w2[(t * FIN + 2 * j + 1) * FIN + l]);
    const float b2 = pre_b2[t * FIN + l];

    {
        float w1c[FIN];
#pragma unroll
        for (int f = 0; f < FIN; f++) w1c[f] = pre_w1[(t * 96 + 64 + f) * FIN + l];
#pragma unroll
        for (int b = 0; b < 5; b++) {
            float et = g_enc[b * FIN + l];
            float a = 0.f;
#pragma unroll
            for (int f = 0; f < FIN; f++) a += __shfl_sync(FULLM, et, f) * w1c[f];
            evtab[t][b][l] = a;
        }
        __syncwarp();
    }
    const float* evs = &evtab[t][0][0];   // lane l reads evs[b*32+l]: bank-conflict-free
    const int off = t * FIN + l;
    const int half = (N + 1) >> 1;

    for (int n = blockIdx.x; n < half; n += gridDim.x) {
        const int nA = n, nB = n + half;
        const bool hasB = nB < N;
        float a0A = g_a0[nA * H + off];
        int e0A = g_off[nA], e1A = g_off[nA + 1];
        float a0B = 0.f; int e0B = 0, e1B = 0;
        if (hasB) { a0B = g_a0[nB * H + off]; e0B = g_off[nB]; e1B = g_off[nB + 1]; }
        const int cntA = e1A - e0A, cntB = e1B - e0B;
        const int pAcnt = cntA >> 1, pBcnt = cntB >> 1;
        const int np = max(pAcnt, pBcnt);

        float sA = 0.f, qA = 0.f, sB = 0.f, qB = 0.f;
        float minA = FLT_MAX, maxA = -FLT_MAX, minB = FLT_MAX, maxB = -FLT_MAX;

        float paA = 0.f, pbA = 0.f, paB = 0.f, pbB = 0.f;
        float evaA = 0.f, evbA = 0.f, evaB = 0.f, evbB = 0.f;
        if (pAcnt > 0) {
            int k0 = g_csr[e0A], k1 = g_csr[e0A + 1];
            evaA = evs[(k0 >> 27) * 32 + l];
            evbA = evs[(k1 >> 27) * 32 + l];
            paA = g_p[(k0 & 0x07ffffff) + off];
            pbA = g_p[(k1 & 0x07ffffff) + off];
        }
        if (pBcnt > 0) {
            int k0 = g_csr[e0B], k1 = g_csr[e0B + 1];
            evaB = evs[(k0 >> 27) * 32 + l];
            evbB = evs[(k1 >> 27) * 32 + l];
            paB = g_p[(k0 & 0x07ffffff) + off];
            pbB = g_p[(k1 & 0x07ffffff) + off];
        }

        for (int i = 0; i < np; i++) {
            const int par = i & 1;
            const bool dA = i < pAcnt, dB = i < pBcnt;
            if (dA) {
                rs[t][par][0][l] = fmaxf(a0A + evaA + paA, 0.f);
                rs[t][par][1][l] = fmaxf(a0A + evbA + pbA, 0.f);
            }
            if (dB) {
                rs[t][par][2][l] = fmaxf(a0B + evaB + paB, 0.f);
                rs[t][par][3][l] = fmaxf(a0B + evbB + pbB, 0.f);
            }
            if (i + 1 < pAcnt) {
                int idx = e0A + 2 * (i + 1);
                int k0 = g_csr[idx], k1 = g_csr[idx + 1];
                evaA = evs[(k0 >> 27) * 32 + l];
                evbA = evs[(k1 >> 27) * 32 + l];
                paA = g_p[(k0 & 0x07ffffff) + off];
                pbA = g_p[(k1 & 0x07ffffff) + off];
            }
            if (i + 1 < pBcnt) {
                int idx = e0B + 2 * (i + 1);
                int k0 = g_csr[idx], k1 = g_csr[idx + 1];
                evaB = evs[(k0 >> 27) * 32 + l];
                evbB = evs[(k1 >> 27) * 32 + l];
                paB = g_p[(k0 & 0x07ffffff) + off];
                pbB = g_p[(k1 & 0x07ffffff) + off];
            }
            __syncwarp();
            if (dA) {
                float m0 = dot_edge(rs[t][par][0], w2d, b2);
                float m1 = dot_edge(rs[t][par][1], w2d, b2);
                sA += m0 + m1;
                qA = fmaf(m0, m0, qA); qA = fmaf(m1, m1, qA);
                minA = fminf(minA, fminf(m0, m1));
                maxA = fmaxf(maxA, fmaxf(m0, m1));
            }
            if (dB) {
                float m0 = dot_edge(rs[t][par][2], w2d, b2);
                float m1 = dot_edge(rs[t][par][3], w2d, b2);
                sB += m0 + m1;
                qB = fmaf(m0, m0, qB); qB = fmaf(m1, m1, qB);
                minB = fminf(minB, fminf(m0, m1));
                maxB = fmaxf(maxB, fmaxf(m0, m1));
            }
        }

        const bool tA = (cntA & 1) != 0, tB = (cntB & 1) != 0;
        if (tA | tB) {
            const int par = np & 1;
            if (tA) {
                int k = g_csr[e1A - 1];
                float p = g_p[(k & 0x07ffffff) + off];
                rs[t][par][0][l] = fmaxf(a0A + evs[(k >> 27) * 32 + l] + p, 0.f);
            }
            if (tB) {
                int k = g_csr[e1B - 1];
                float p = g_p[(k & 0x07ffffff) + off];
                rs[t][par][2][l] = fmaxf(a0B + evs[(k >> 27) * 32 + l] + p, 0.f);
            }
            __syncwarp();
            if (tA) {
                float m0 = dot_edge(rs[t][par][0], w2d, b2);
                sA += m0; qA = fmaf(m0, m0, qA);
                minA = fminf(minA, m0); maxA = fmaxf(maxA, m0);
            }
            if (tB) {
                float m0 = dot_edge(rs[t][par][2], w2d, b2);
                sB += m0; qB = fmaf(m0, m0, qB);
                minB = fminf(minB, m0); maxB = fmaxf(maxB, m0);
            }
        }

        {
            float c1 = fmaxf((float)cntA, 1.f);
            float mean = sA / c1;
            float stdv = sqrtf(fmaxf(qA / c1 - mean * mean, 0.f) + 1e-5f);
            float mn = minA, mx = maxA;
            if (cntA == 0) { mn = 0.f; mx = 0.f; }
            float* o = g_agg + (size_t)(nA * T + t) * 5 * FIN + l;
            o[0 * FIN] = sA; o[1 * FIN] = mean; o[2 * FIN] = mn;
            o[3 * FIN] = mx; o[4 * FIN] = stdv;
        }
        if (hasB) {
            float c1 = fmaxf((float)cntB, 1.f);
            float mean = sB / c1;
            float stdv = sqrtf(fmaxf(qB / c1 - mean * mean, 0.f) + 1e-5f);
            float mn = minB, mx = maxB;
            if (cntB == 0) { mn = 0.f; mx = 0.f; }
            float* o = g_agg + (size_t)(nB * T + t) * 5 * FIN + l;
            o[0 * FIN] = sB; o[1 * FIN] = mean; o[2 * FIN] = mn;
            o[3 * FIN] = mx; o[4 * FIN] = stdv;
        }
    }
}

// ---------------- fused tail: post-MLP (all 4 towers) + final linear + LayerNorm ----------------
__global__ void __launch_bounds__(128, 4) k_tail(
    const float* __restrict__ atom_x,
    const float* __restrict__ post_w1, const float* __restrict__ post_b1,
    const float* __restrict__ post_w2, const float* __restrict__ post_b2,
    const float* __restrict__ lin_w, const float* __restrict__ lin_b,
    const float* __restrict__ ln_g, const float* __restrict__ ln_b,
    float* __restrict__ out, int N) {
    const int w = threadIdx.x >> 5;
    const int g = threadIdx.x & 31;
    __shared__ __align__(16) float st[16][512];     // 32 KB, re-staged per tower
    __shared__ float red[4][16][32];                // 8 KB
    __shared__ float s1s[16], s2s[16];

    const int n0 = blockIdx.x * 16;

    if (threadIdx.x < 16) {
        int n = min(n0 + threadIdx.x, N - 1);
        float avg = g_avg_log;
        float c1 = fmaxf((float)g_deg[n], 1.f);
        float logd = logf(c1 + 1.f);
        s1s[threadIdx.x] = logd / avg;
        s2s[threadIdx.x] = avg / logd;
    }
    ull facc[4][2];
#pragma unroll
    for (int j2 = 0; j2 < 4; j2++) { facc[j2][0] = 0ull; facc[j2][1] = 0ull; }
    __syncthreads();

    for (int t = 0; t < T; t++) {
#pragma unroll
        for (int j2 = 0; j2 < 4; j2++) {
            const int j = w * 4 + j2;
            const int n = min(n0 + j, N - 1);
            float s1 = s1s[j], s2 = s2s[j];
            st[j][g] = atom_x[n * H + t * FIN + g];
            const float* ag = g_agg + (size_t)(n * T + t) * 5 * FIN;
#pragma unroll
            for (int a = 0; a < 5; a++) {
                float v = ag[a * FIN + g];
                st[j][32 + a * FIN + g] = v;
                st[j][192 + a * FIN + g] = v * s1;
                st[j][352 + a * FIN + g] = v * s2;
            }
        }
        __syncthreads();

        const float* wbase = post_w1 + (size_t)t * 512 * FIN + (size_t)(w * 128) * FIN + g;
        const int fbase = w * 128;
        ull acc[16];
#pragma unroll
        for (int nd = 0; nd < 16; nd++) acc[nd] = 0ull;
#pragma unroll 4
        for (int fq = 0; fq < 32; fq++) {
            const int f = fbase + 4 * fq;
            float wv0 = wbase[(4 * fq + 0) * FIN];
            float wv1 = wbase[(4 * fq + 1) * FIN];
            float wv2 = wbase[(4 * fq + 2) * FIN];
            float wv3 = wbase[(4 * fq + 3) * FIN];
            ull wd0 = packf2(wv0, wv1);
            ull wd1 = packf2(wv2, wv3);
#pragma unroll
            for (int nd = 0; nd < 16; nd++) {
                ulonglong2 v = *(const ulonglong2*)&st[nd][f];
                acc[nd] = fma2(v.x, wd0, acc[nd]);
                acc[nd] = fma2(v.y, wd1, acc[nd]);
            }
        }
#pragma unroll
        for (int nd = 0; nd < 16; nd++) {
            float lo, hi; unpackf2(acc[nd], lo, hi);
            red[w][nd][g] = lo + hi;
        }
        __syncthreads();

        const float b1 = post_b1[t * FIN + g];
        const float b2v = post_b2[t * FIN + g];
        const int j = w * 4;
        float m0 = fmaxf(red[0][j+0][g] + red[1][j+0][g] + red[2][j+0][g] + red[3][j+0][g] + b1, 0.f);
        float m1 = fmaxf(red[0][j+1][g] + red[1][j+1][g] + red[2][j+1][g] + red[3][j+1][g] + b1, 0.f);
        float m2 = fmaxf(red[0][j+2][g] + red[1][j+2][g] + red[2][j+2][g] + red[3][j+2][g] + b1, 0.f);
        float m3 = fmaxf(red[0][j+3][g] + red[1][j+3][g] + red[2][j+3][g] + red[3][j+3][g] + b1, 0.f);
        float o0 = b2v, o1 = b2v, o2 = b2v, o3 = b2v;
#pragma unroll
        for (int f = 0; f < FIN; f++) {
            float wv = __ldg(&post_w2[(t * FIN + f) * FIN + g]);
            o0 += __shfl_sync(FULLM, m0, f) * wv;
            o1 += __shfl_sync(FULLM, m1, f) * wv;
            o2 += __shfl_sync(FULLM, m2, f) * wv;
            o3 += __shfl_sync(FULLM, m3, f) * wv;
        }
#pragma unroll
        for (int f = 0; f < FIN; f++) {
            const float* lw = lin_w + (size_t)(t * FIN + f) * H + g;
            ull wda = packf2(__ldg(&lw[0]),  __ldg(&lw[32]));
            ull wdb = packf2(__ldg(&lw[64]), __ldg(&lw[96]));
            float y0 = __shfl_sync(FULLM, o0, f);
            float y1 = __shfl_sync(FULLM, o1, f);
            float y2 = __shfl_sync(FULLM, o2, f);
            float y3 = __shfl_sync(FULLM, o3, f);
            ull yd0 = packf2(y0, y0), yd1 = packf2(y1, y1);
            ull yd2 = packf2(y2, y2), yd3 = packf2(y3, y3);
            facc[0][0] = fma2(yd0, wda, facc[0][0]); facc[0][1] = fma2(yd0, wdb, facc[0][1]);
            facc[1][0] = fma2(yd1, wda, facc[1][0]); facc[1][1] = fma2(yd1, wdb, facc[1][1]);
            facc[2][0] = fma2(yd2, wda, facc[2][0]); facc[2][1] = fma2(yd2, wdb, facc[2][1]);
            facc[3][0] = fma2(yd3, wda, facc[3][0]); facc[3][1] = fma2(yd3, wdb, facc[3][1]);
        }
        __syncthreads();
    }

    const float lb0 = lin_b[g],      lb1 = lin_b[32 + g];
    const float lb2 = lin_b[64 + g], lb3 = lin_b[96 + g];
    const float ga0 = ln_g[g],      ga1 = ln_g[32 + g];
    const float ga2 = ln_g[64 + g], ga3 = ln_g[96 + g];
    const float be0 = ln_b[g],      be1 = ln_b[32 + g];
    const float be2 = ln_b[64 + g], be3 = ln_b[96 + g];

#pragma unroll
    for (int j2 = 0; j2 < 4; j2++) {
        int n = n0 + w * 4 + j2;
        float a0, a1, a2, a3;
        unpackf2(facc[j2][0], a0, a1);
        unpackf2(facc[j2][1], a2, a3);
        a0 += lb0; a1 += lb1; a2 += lb2; a3 += lb3;
        float s = a0 + a1 + a2 + a3;
        float q = a0 * a0 + a1 * a1 + a2 * a2 + a3 * a3;
#pragma unroll
        for (int off = 16; off > 0; off >>= 1) {
            s += __shfl_xor_sync(FULLM, s, off);
            q += __shfl_xor_sync(FULLM, q, off);
        }
        if (n < N) {
            float mu = s * (1.f / 128.f);
            float var = q * (1.f / 128.f) - mu * mu;
            float rstd = rsqrtf(var + 1e-5f);
            const float* ax = atom_x + (size_t)n * H;
            float* op = out + (size_t)n * H;
            op[g]      = ax[g]      + fmaxf((a0 - mu) * rstd * ga0 + be0, 0.f);
            op[32 + g] = ax[32 + g] + fmaxf((a1 - mu) * rstd * ga1 + be1, 0.f);
            op[64 + g] = ax[64 + g] + fmaxf((a2 - mu) * rstd * ga2 + be2, 0.f);
            op[96 + g] = ax[96 + g] + fmaxf((a3 - mu) * rstd * ga3 + be3, 0.f);
        }
    }
}

// ---------------- launch ----------------
extern "C" void kernel_launch(void* const* d_in, const int* in_sizes, int n_in,
                              void* d_out, int out_size) {
    const float* atom_x  = (const float*)d_in[0];
    const int*   bond_x  = (const int*)d_in[1];
    const int*   edge_ix = (const int*)d_in[2];
    const int*   mol_deg = (const int*)d_in[3];
    const float* bond_emb = (const float*)d_in[4];
    const float* enc_w   = (const float*)d_in[5];
    const float* enc_b   = (const float*)d_in[6];
    const float* pre_w1  = (const float*)d_in[7];
    const float* pre_b1  = (const float*)d_in[8];
    const float* pre_w2  = (const float*)d_in[9];
    const float* pre_b2  = (const float*)d_in[10];
    const float* post_w1 = (const float*)d_in[11];
    const float* post_b1 = (const float*)d_in[12];
    const float* post_w2 = (const float*)d_in[13];
    const float* post_b2 = (const float*)d_in[14];
    const float* lin_w   = (const float*)d_in[15];
    const float* lin_b   = (const float*)d_in[16];
    const float* ln_g    = (const float*)d_in[17];
    const float* ln_b    = (const float*)d_in[18];
    float* out = (float*)d_out;

    int N = in_sizes[0] / H;
    int E = in_sizes[1];
    const int* src = edge_ix;
    const int* dst = edge_ix + E;

    k_setup<<<NB, STH>>>(dst, src, bond_x, atom_x, pre_w1, pre_b1,
                         mol_deg, bond_emb, enc_w, enc_b, N, E);            // 0 <- ncu verify
    k_agg<<<888, 128>>>(pre_w1, pre_w2, pre_b2, N);                         // 1
    k_tail<<<(N + 15) / 16, 128>>>(atom_x, post_w1, post_b1, post_w2, post_b2,
                                   lin_w, lin_b, ln_g, ln_b, out, N);       // 2
}